// round 4
// baseline (speedup 1.0000x reference)
#include <cuda_runtime.h>
#include <math.h>

#define HW 16384
#define IMG_W 128
#define DIM 192
#define HEADS 4
#define DHEAD 48
#define HIDDEN 510
#define BATCH 4

// ---------------- scratch (static device arrays; no cudaMalloc allowed) --------
__device__ float g_S0[BATCH * 1020 * HW];        // conv1x1 outputs (qkv:576 / pin:1020)
__device__ float g_S1[BATCH * 576 * HW];         // dw outputs (qkv) / gated gdfn (510)
__device__ float g_S2[BATCH * DIM * HW];         // attention output
__device__ float g_mean[BATCH * HW];             // LN per-pixel mean
__device__ float g_istd[BATCH * HW];             // LN per-pixel inv std
__device__ float g_rn[BATCH * 2 * DIM];          // inverse L2 norms q,k rows
__device__ float g_rnpart[BATCH * 2 * DIM * 64]; // per-block sumsq partials
__device__ float g_A[16 * DHEAD * DHEAD];        // softmaxed attention
__device__ float g_Apart[16 * 16 * DHEAD * DHEAD];

// ---------------- f32x2 helpers (Blackwell packed fp32) -------------------------
__device__ __forceinline__ unsigned long long pk2(float v) {
    unsigned long long r;
    asm("mov.b64 %0, {%1, %1};" : "=l"(r) : "f"(v));
    return r;
}
__device__ __forceinline__ void fma2(unsigned long long& d,
                                     unsigned long long a, unsigned long long b) {
    asm("fma.rn.f32x2 %0, %1, %2, %0;" : "+l"(d) : "l"(a), "l"(b));
}
__device__ __forceinline__ float2 up2(unsigned long long v) {
    float2 f;
    asm("mov.b64 {%0, %1}, %2;" : "=f"(f.x), "=f"(f.y) : "l"(v));
    return f;
}

// ---------------- per-pixel LN stats (mean, inv-std over 192 channels) ----------
__global__ __launch_bounds__(256) void ln_stats_kernel(const float* __restrict__ x,
                                                       float* __restrict__ mean,
                                                       float* __restrict__ istd) {
    int n = blockIdx.x * 256 + threadIdx.x;
    int b = blockIdx.y;
    const float* xb = x + (long long)b * DIM * HW + n;
    float s = 0.f, s2 = 0.f;
#pragma unroll 8
    for (int c = 0; c < DIM; c++) {
        float v = xb[(long long)c * HW];
        s += v; s2 += v * v;
    }
    float m = s * (1.f / DIM);
    float var = s2 * (1.f / DIM) - m * m;
    mean[b * HW + n] = m;
    istd[b * HW + n] = rsqrtf(var + 1e-6f);
}

// ---------------- GEMM: Out[b,m,n] = sum_k W[m,k]*Bval[k,n] (+Res) --------------
// Bval = X (raw) or LN-normalized on the fly when lnMean != nullptr.
// BM=64, BN=128, BK=16, 256 threads, 4x8 microtile via packed f32x2.
__global__ __launch_bounds__(256) void gemm_kernel(const float* __restrict__ Wm,
                                                   const float* __restrict__ X,
                                                   float* __restrict__ Out,
                                                   const float* __restrict__ Res,
                                                   const float* __restrict__ lnMean,
                                                   const float* __restrict__ lnIstd,
                                                   const float* __restrict__ lnW,
                                                   int M, int K,
                                                   long long xbs, long long obs,
                                                   int addRes) {
    __shared__ float As[16][68];    // [k][m] padded
    __shared__ float Bs[16][128];   // [k][n]
    int tid = threadIdx.x;
    int n0 = blockIdx.x * 128;
    int m0 = blockIdx.y * 64;
    int b  = blockIdx.z;
    const float* Xb = X + (long long)b * xbs;
    const float* Mb = lnMean ? lnMean + (long long)b * HW : nullptr;
    const float* Ib = lnMean ? lnIstd + (long long)b * HW : nullptr;

    int tx = tid & 15, ty = tid >> 4;
    unsigned long long acc[4][4];
#pragma unroll
    for (int i = 0; i < 4; i++)
#pragma unroll
        for (int j = 0; j < 4; j++) acc[i][j] = 0ULL;

    // A-load indices: 64 rows x 16 k = 1024 floats, 4 scalars/thread
    int am = tid >> 2;               // 0..63
    int ak0 = (tid & 3) * 4;         // 0,4,8,12
    // B-load indices: 16 k x 128 n = 2048 floats = 512 float4, 2/thread
    for (int k0 = 0; k0 < K; k0 += 16) {
        // ---- load A (W[m,k]) transposed into As[k][m]
#pragma unroll
        for (int j = 0; j < 4; j++) {
            int m = m0 + am, k = k0 + ak0 + j;
            As[ak0 + j][am] = (m < M && k < K) ? Wm[(long long)m * K + k] : 0.f;
        }
        // ---- load B
#pragma unroll
        for (int i = 0; i < 2; i++) {
            int f4 = tid + i * 256;          // 0..511
            int bk = f4 >> 5;                // 0..15
            int bn = (f4 & 31) * 4;          // 0..124
            int k = k0 + bk;
            float4 v = make_float4(0.f, 0.f, 0.f, 0.f);
            if (k < K) {
                v = *(const float4*)&Xb[(long long)k * HW + n0 + bn];
                if (lnMean) {
                    float4 mm = *(const float4*)&Mb[n0 + bn];
                    float4 ii = *(const float4*)&Ib[n0 + bn];
                    float wk = lnW[k];
                    v.x = (v.x - mm.x) * ii.x * wk;
                    v.y = (v.y - mm.y) * ii.y * wk;
                    v.z = (v.z - mm.z) * ii.z * wk;
                    v.w = (v.w - mm.w) * ii.w * wk;
                }
            }
            *(float4*)&Bs[bk][bn] = v;
        }
        __syncthreads();
#pragma unroll
        for (int kk = 0; kk < 16; kk++) {
            float4 av = *(const float4*)&As[kk][ty * 4];
            const unsigned long long* bp0 = (const unsigned long long*)&Bs[kk][tx * 4];
            const unsigned long long* bp1 = (const unsigned long long*)&Bs[kk][64 + tx * 4];
            unsigned long long b0 = bp0[0], b1 = bp0[1], b2 = bp1[0], b3 = bp1[1];
            unsigned long long a0 = pk2(av.x), a1 = pk2(av.y), a2 = pk2(av.z), a3 = pk2(av.w);
            fma2(acc[0][0], a0, b0); fma2(acc[0][1], a0, b1); fma2(acc[0][2], a0, b2); fma2(acc[0][3], a0, b3);
            fma2(acc[1][0], a1, b0); fma2(acc[1][1], a1, b1); fma2(acc[1][2], a1, b2); fma2(acc[1][3], a1, b3);
            fma2(acc[2][0], a2, b0); fma2(acc[2][1], a2, b1); fma2(acc[2][2], a2, b2); fma2(acc[2][3], a2, b3);
            fma2(acc[3][0], a3, b0); fma2(acc[3][1], a3, b1); fma2(acc[3][2], a3, b2); fma2(acc[3][3], a3, b3);
        }
        __syncthreads();
    }

    float* Ob = Out + (long long)b * obs;
    const float* Rb = Res + (long long)b * obs;
#pragma unroll
    for (int i = 0; i < 4; i++) {
        int m = m0 + ty * 4 + i;
        if (m >= M) continue;
        float2 p0 = up2(acc[i][0]), p1 = up2(acc[i][1]);
        float2 p2 = up2(acc[i][2]), p3 = up2(acc[i][3]);
        long long off0 = (long long)m * HW + n0 + tx * 4;
        long long off1 = off0 + 64;
        float4 v0 = make_float4(p0.x, p0.y, p1.x, p1.y);
        float4 v1 = make_float4(p2.x, p2.y, p3.x, p3.y);
        if (addRes) {
            float4 r0 = *(const float4*)&Rb[off0];
            float4 r1 = *(const float4*)&Rb[off1];
            v0.x += r0.x; v0.y += r0.y; v0.z += r0.z; v0.w += r0.w;
            v1.x += r1.x; v1.y += r1.y; v1.z += r1.z; v1.w += r1.w;
        }
        *(float4*)&Ob[off0] = v0;
        *(float4*)&Ob[off1] = v1;
    }
}

// ---------------- depthwise 3x3 for qkv (576 ch) + q/k sumsq partials -----------
__global__ __launch_bounds__(256) void dw_qkv_kernel(const float* __restrict__ in,
                                                     const float* __restrict__ w9,
                                                     float* __restrict__ out) {
    int c = blockIdx.y, b = blockIdx.z;
    long long base = ((long long)b * 576 + c) * HW;
    const float* ib = in + base;
    float w[9];
#pragma unroll
    for (int i = 0; i < 9; i++) w[i] = w9[c * 9 + i];
    int n = blockIdx.x * 256 + threadIdx.x;
    int y = n >> 7, x = n & 127;
    float s = 0.f;
#pragma unroll
    for (int ky = 0; ky < 3; ky++) {
        int iy = y + ky - 1;
        if ((unsigned)iy >= IMG_W) continue;
#pragma unroll
        for (int kx = 0; kx < 3; kx++) {
            int ix = x + kx - 1;
            if ((unsigned)ix >= IMG_W) continue;
            s += w[ky * 3 + kx] * ib[iy * IMG_W + ix];
        }
    }
    out[base + n] = s;
    if (c < 384) {  // q,k channels: accumulate block-partial sum of squares
        __shared__ float red[256];
        red[threadIdx.x] = s * s;
        __syncthreads();
        for (int st = 128; st; st >>= 1) {
            if (threadIdx.x < st) red[threadIdx.x] += red[threadIdx.x + st];
            __syncthreads();
        }
        if (threadIdx.x == 0)
            g_rnpart[((long long)b * 384 + c) * 64 + blockIdx.x] = red[0];
    }
}

// ---------------- reduce sumsq partials -> inverse norms -------------------------
__global__ __launch_bounds__(256) void rn_reduce_kernel() {
    int r = blockIdx.x * 256 + threadIdx.x;   // 0..1535
    if (r >= BATCH * 384) return;
    float s = 0.f;
#pragma unroll 8
    for (int p = 0; p < 64; p++) s += g_rnpart[(long long)r * 64 + p];
    g_rn[r] = 1.f / fmaxf(sqrtf(s), 1e-12f);
}

// ---------------- split-K partial Q.K^T -----------------------------------------
__global__ __launch_bounds__(256) void attn_part_kernel() {
    int chunk = blockIdx.x;
    int bh = blockIdx.y;
    int b = bh >> 2, h = bh & 3;
    const float* qb = g_S1 + ((long long)b * 576 + h * DHEAD) * HW;
    const float* kb = g_S1 + ((long long)b * 576 + DIM + h * DHEAD) * HW;
    __shared__ float sq[48][65], sk[48][65];
    int tid = threadIdx.x;
    int tc = tid & 15, tr = tid >> 4;
    int c0 = tr * 3, d0 = tc * 3;
    float acc[3][3] = {};
    long long nbase = (long long)chunk * 1024;
    for (int nn = 0; nn < 1024; nn += 64) {
#pragma unroll
        for (int i = 0; i < 12; i++) {
            int idx = tid + i * 256;
            int r = idx >> 6, col = idx & 63;
            sq[r][col] = qb[(long long)r * HW + nbase + nn + col];
            sk[r][col] = kb[(long long)r * HW + nbase + nn + col];
        }
        __syncthreads();
#pragma unroll
        for (int kk = 0; kk < 64; kk++) {
            float q0 = sq[c0][kk], q1 = sq[c0 + 1][kk], q2 = sq[c0 + 2][kk];
            float k0 = sk[d0][kk], k1 = sk[d0 + 1][kk], k2 = sk[d0 + 2][kk];
            acc[0][0] += q0 * k0; acc[0][1] += q0 * k1; acc[0][2] += q0 * k2;
            acc[1][0] += q1 * k0; acc[1][1] += q1 * k1; acc[1][2] += q1 * k2;
            acc[2][0] += q2 * k0; acc[2][1] += q2 * k1; acc[2][2] += q2 * k2;
        }
        __syncthreads();
    }
    float* P = g_Apart + ((long long)bh * 16 + chunk) * (DHEAD * DHEAD);
#pragma unroll
    for (int i = 0; i < 3; i++)
#pragma unroll
        for (int j = 0; j < 3; j++)
            P[(c0 + i) * DHEAD + d0 + j] = acc[i][j];
}

// ---------------- reduce partials, scale, softmax --------------------------------
__global__ __launch_bounds__(256) void attn_finish_kernel(const float* __restrict__ temp) {
    int bh = blockIdx.x;
    int b = bh >> 2, h = bh & 3;
    __shared__ float sA[DHEAD * DHEAD];
    int tid = threadIdx.x;
    for (int i = tid; i < DHEAD * DHEAD; i += 256) {
        float s = 0.f;
        for (int p = 0; p < 16; p++)
            s += g_Apart[((long long)bh * 16 + p) * (DHEAD * DHEAD) + i];
        int c = i / DHEAD, d = i % DHEAD;
        float scale = g_rn[b * 384 + h * DHEAD + c] *
                      g_rn[b * 384 + DIM + h * DHEAD + d] * temp[h];
        sA[i] = s * scale;
    }
    __syncthreads();
    if (tid < DHEAD) {
        float mx = -1e30f;
        for (int d = 0; d < DHEAD; d++) mx = fmaxf(mx, sA[tid * DHEAD + d]);
        float sum = 0.f;
        for (int d = 0; d < DHEAD; d++) sum += __expf(sA[tid * DHEAD + d] - mx);
        float inv = 1.f / sum;
        for (int d = 0; d < DHEAD; d++)
            g_A[bh * DHEAD * DHEAD + tid * DHEAD + d] =
                __expf(sA[tid * DHEAD + d] - mx) * inv;
    }
}

// ---------------- out = A @ V ----------------------------------------------------
__global__ __launch_bounds__(256) void av_kernel() {
    int bh = blockIdx.y;
    int b = bh >> 2, h = bh & 3;
    __shared__ float sA[DHEAD][DHEAD];
    int tid = threadIdx.x;
    for (int i = tid; i < DHEAD * DHEAD; i += 256)
        sA[i / DHEAD][i % DHEAD] = g_A[bh * DHEAD * DHEAD + i];
    __syncthreads();
    int n = blockIdx.x * 256 + tid;
    const float* vb = g_S1 + ((long long)b * 576 + 2 * DIM + h * DHEAD) * HW + n;
    float v[DHEAD];
#pragma unroll
    for (int d = 0; d < DHEAD; d++) v[d] = vb[(long long)d * HW];
    float* ob = g_S2 + ((long long)b * DIM + h * DHEAD) * HW + n;
#pragma unroll 4
    for (int c = 0; c < DHEAD; c++) {
        float s = 0.f;
#pragma unroll
        for (int d = 0; d < DHEAD; d++) s += sA[c][d] * v[d];
        ob[(long long)c * HW] = s;
    }
}

// ---------------- fused GDFN depthwise 3x3 + GELU gate ---------------------------
// reads S0 channels c and c+510, writes gelu(dw1)*dw2 to S1 (510-ch layout)
__global__ __launch_bounds__(256) void dw_gate_kernel(const float* __restrict__ in,
                                                      const float* __restrict__ w9,
                                                      float* __restrict__ out) {
    int c = blockIdx.y, b = blockIdx.z;
    const float* ib1 = in + ((long long)b * 1020 + c) * HW;
    const float* ib2 = in + ((long long)b * 1020 + HIDDEN + c) * HW;
    float w1[9], w2[9];
#pragma unroll
    for (int i = 0; i < 9; i++) { w1[i] = w9[c * 9 + i]; w2[i] = w9[(HIDDEN + c) * 9 + i]; }
    int n = blockIdx.x * 256 + threadIdx.x;
    int y = n >> 7, x = n & 127;
    float s1 = 0.f, s2 = 0.f;
#pragma unroll
    for (int ky = 0; ky < 3; ky++) {
        int iy = y + ky - 1;
        if ((unsigned)iy >= IMG_W) continue;
#pragma unroll
        for (int kx = 0; kx < 3; kx++) {
            int ix = x + kx - 1;
            if ((unsigned)ix >= IMG_W) continue;
            float v1 = ib1[iy * IMG_W + ix];
            float v2 = ib2[iy * IMG_W + ix];
            s1 += w1[ky * 3 + kx] * v1;
            s2 += w2[ky * 3 + kx] * v2;
        }
    }
    float g = 0.5f * s1 * (1.f + erff(s1 * 0.70710678118654752f));
    out[((long long)b * HIDDEN + c) * HW + n] = g * s2;
}

// =============================================================================
extern "C" void kernel_launch(void* const* d_in, const int* in_sizes, int n_in,
                              void* d_out, int out_size) {
    const float* x     = (const float*)d_in[0];
    const float* n1w   = (const float*)d_in[1];
    const float* qkvw  = (const float*)d_in[2];
    const float* qkvdw = (const float*)d_in[3];
    const float* temp  = (const float*)d_in[4];
    const float* projw = (const float*)d_in[5];
    const float* n2w   = (const float*)d_in[6];
    const float* pinw  = (const float*)d_in[7];
    const float* dww   = (const float*)d_in[8];
    const float* poutw = (const float*)d_in[9];
    float* out = (float*)d_out;

    float *S0, *S1, *S2, *Mn, *Is;
    cudaGetSymbolAddress((void**)&S0, g_S0);
    cudaGetSymbolAddress((void**)&S1, g_S1);
    cudaGetSymbolAddress((void**)&S2, g_S2);
    cudaGetSymbolAddress((void**)&Mn, g_mean);
    cudaGetSymbolAddress((void**)&Is, g_istd);

    dim3 pxGrid(HW / 256, BATCH);

    // ---- MDTA branch ----
    ln_stats_kernel<<<pxGrid, 256>>>(x, Mn, Is);

    // qkv 1x1 (LN fused): 576 x 192
    gemm_kernel<<<dim3(HW / 128, 9, BATCH), 256>>>(
        qkvw, x, S0, nullptr, Mn, Is, n1w,
        576, DIM, (long long)DIM * HW, (long long)576 * HW, 0);

    dw_qkv_kernel<<<dim3(HW / 256, 576, BATCH), 256>>>(S0, qkvdw, S1);
    rn_reduce_kernel<<<6, 256>>>();
    attn_part_kernel<<<dim3(16, 16), 256>>>();
    attn_finish_kernel<<<16, 256>>>(temp);
    av_kernel<<<dim3(HW / 256, 16), 256>>>();

    // proj 1x1 (192x192) + residual(x) -> d_out
    gemm_kernel<<<dim3(HW / 128, 3, BATCH), 256>>>(
        projw, S2, out, x, nullptr, nullptr, nullptr,
        DIM, DIM, (long long)DIM * HW, (long long)DIM * HW, 1);

    // ---- GDFN branch ----
    ln_stats_kernel<<<pxGrid, 256>>>(out, Mn, Is);

    // pin 1x1 (LN fused): 1020 x 192
    gemm_kernel<<<dim3(HW / 128, 16, BATCH), 256>>>(
        pinw, out, S0, nullptr, Mn, Is, n2w,
        1020, DIM, (long long)DIM * HW, (long long)1020 * HW, 0);

    dw_gate_kernel<<<dim3(HW / 256, HIDDEN, BATCH), 256>>>(S0, dww, S1);

    // pout 1x1 (192x510) + residual(d_out) -> d_out
    gemm_kernel<<<dim3(HW / 128, 3, BATCH), 256>>>(
        poutw, S1, out, out, nullptr, nullptr, nullptr,
        DIM, HIDDEN, (long long)HIDDEN * HW, (long long)DIM * HW, 1);
}

// round 5
// speedup vs baseline: 1.4215x; 1.4215x over previous
#include <cuda_runtime.h>
#include <math.h>
#include <stdint.h>

#define HW 16384
#define IMG_W 128
#define DIM 192
#define HEADS 4
#define DHEAD 48
#define HIDDEN 510
#define BATCH 4

// ---------------- scratch (static device arrays; no cudaMalloc allowed) --------
__device__ float g_S0[BATCH * 1020 * HW];        // conv1x1 outputs (qkv:576 / pin:1020)
__device__ float g_S1[BATCH * 576 * HW];         // dw outputs (qkv) / gated gdfn (510)
__device__ float g_S2[BATCH * DIM * HW];         // attention output
__device__ float g_mean[BATCH * HW];             // LN per-pixel mean
__device__ float g_istd[BATCH * HW];             // LN per-pixel inv std
__device__ float g_rn[BATCH * 2 * DIM];          // inverse L2 norms q,k rows
__device__ float g_rnpart[64 * BATCH * 2 * DIM]; // per-block sumsq partials [p][r]
__device__ float g_A[16 * DHEAD * DHEAD];        // softmaxed attention
__device__ float g_Apart[16 * 16 * DHEAD * DHEAD];

// ---------------- tf32 helper ---------------------------------------------------
__device__ __forceinline__ uint32_t f2tf32(float f) {
    uint32_t u;
    asm("cvt.rna.tf32.f32 %0, %1;" : "=r"(u) : "f"(f));
    return u;
}
__device__ __forceinline__ void mma_tf32(float* d, const uint32_t* a, const uint32_t* b) {
    asm volatile(
        "mma.sync.aligned.m16n8k8.row.col.f32.tf32.tf32.f32 "
        "{%0,%1,%2,%3}, {%4,%5,%6,%7}, {%8,%9}, {%0,%1,%2,%3};"
        : "+f"(d[0]), "+f"(d[1]), "+f"(d[2]), "+f"(d[3])
        : "r"(a[0]), "r"(a[1]), "r"(a[2]), "r"(a[3]), "r"(b[0]), "r"(b[1]));
}

// ---------------- per-pixel LN stats (mean, inv-std over 192 channels) ----------
__global__ __launch_bounds__(256) void ln_stats_kernel(const float* __restrict__ x,
                                                       float* __restrict__ mean,
                                                       float* __restrict__ istd) {
    int n = blockIdx.x * 256 + threadIdx.x;
    int b = blockIdx.y;
    const float* xb = x + (long long)b * DIM * HW + n;
    float s = 0.f, s2 = 0.f;
#pragma unroll 8
    for (int c = 0; c < DIM; c++) {
        float v = xb[(long long)c * HW];
        s += v; s2 += v * v;
    }
    float m = s * (1.f / DIM);
    float var = s2 * (1.f / DIM) - m * m;
    mean[b * HW + n] = m;
    istd[b * HW + n] = rsqrtf(var + 1e-6f);
}

// ---------------- tf32 tensor-core GEMM -----------------------------------------
// Out[b,m,n] = sum_k W[m,k] * Bval[k,n] (+Res); Bval optionally LN-normalized.
// BM=64, BN=128, BK=16; 256 threads = 8 warps in 2(M) x 4(N); warp tile 32x32.
__global__ __launch_bounds__(256) void gemm_tc(const float* __restrict__ Wm,
                                               const float* __restrict__ X,
                                               float* __restrict__ Out,
                                               const float* __restrict__ Res,
                                               const float* __restrict__ lnMean,
                                               const float* __restrict__ lnIstd,
                                               const float* __restrict__ lnW,
                                               int M, int K,
                                               long long xbs, long long obs,
                                               int addRes) {
    __shared__ __align__(16) uint32_t As[16][72];    // [k][m], pad->conflict-free
    __shared__ __align__(16) uint32_t Bs[16][136];   // [k][n], pad->conflict-free
    int tid = threadIdx.x;
    int lane = tid & 31, wid = tid >> 5;
    int wm = wid & 1, wn = wid >> 1;               // warp coords
    int ra = lane >> 2, ca = lane & 3;             // fragment lane decomposition
    int n0 = blockIdx.x * 128;
    int m0 = blockIdx.y * 64;
    int b  = blockIdx.z;
    const float* Xb = X + (long long)b * xbs;
    const float* Mb = lnMean ? lnMean + (long long)b * HW : nullptr;
    const float* Ib = lnMean ? lnIstd + (long long)b * HW : nullptr;

    float acc[2][4][4];
#pragma unroll
    for (int i = 0; i < 2; i++)
#pragma unroll
        for (int j = 0; j < 4; j++)
#pragma unroll
            for (int q = 0; q < 4; q++) acc[i][j][q] = 0.f;

    int am = tid >> 2;              // 0..63 (A row)
    int ak0 = (tid & 3) * 4;        // 0,4,8,12 (A k group)

    for (int k0 = 0; k0 < K; k0 += 16) {
        // ---- stage global loads in registers
        float a_st[4];
#pragma unroll
        for (int j = 0; j < 4; j++) {
            int m = m0 + am, k = k0 + ak0 + j;
            a_st[j] = (m < M && k < K) ? Wm[(long long)m * K + k] : 0.f;
        }
        float4 b_st[2];
#pragma unroll
        for (int i = 0; i < 2; i++) {
            int f4 = tid + i * 256;          // 0..511
            int bk = f4 >> 5;                // 0..15
            int bn = (f4 & 31) * 4;          // 0..124
            int k = k0 + bk;
            float4 v = make_float4(0.f, 0.f, 0.f, 0.f);
            if (k < K) {
                v = *(const float4*)&Xb[(long long)k * HW + n0 + bn];
                if (lnMean) {
                    float4 mm = *(const float4*)&Mb[n0 + bn];
                    float4 ii = *(const float4*)&Ib[n0 + bn];
                    float wk = lnW[k];
                    v.x = (v.x - mm.x) * ii.x * wk;
                    v.y = (v.y - mm.y) * ii.y * wk;
                    v.z = (v.z - mm.z) * ii.z * wk;
                    v.w = (v.w - mm.w) * ii.w * wk;
                }
            }
            b_st[i] = v;
        }
        __syncthreads();
#pragma unroll
        for (int j = 0; j < 4; j++) As[ak0 + j][am] = f2tf32(a_st[j]);
#pragma unroll
        for (int i = 0; i < 2; i++) {
            int f4 = tid + i * 256;
            int bk = f4 >> 5;
            int bn = (f4 & 31) * 4;
            uint4 u = make_uint4(f2tf32(b_st[i].x), f2tf32(b_st[i].y),
                                 f2tf32(b_st[i].z), f2tf32(b_st[i].w));
            *(uint4*)&Bs[bk][bn] = u;
        }
        __syncthreads();

        // ---- 2 k-steps of 8
#pragma unroll
        for (int ks = 0; ks < 2; ks++) {
            int kb = ks * 8;
            uint32_t afr[2][4], bfr[4][2];
#pragma unroll
            for (int tm = 0; tm < 2; tm++) {
                int m = wm * 32 + tm * 16 + ra;
                afr[tm][0] = As[kb + ca][m];
                afr[tm][1] = As[kb + ca][m + 8];
                afr[tm][2] = As[kb + ca + 4][m];
                afr[tm][3] = As[kb + ca + 4][m + 8];
            }
#pragma unroll
            for (int tn = 0; tn < 4; tn++) {
                int n = wn * 32 + tn * 8 + ra;
                bfr[tn][0] = Bs[kb + ca][n];
                bfr[tn][1] = Bs[kb + ca + 4][n];
            }
#pragma unroll
            for (int tm = 0; tm < 2; tm++)
#pragma unroll
                for (int tn = 0; tn < 4; tn++)
                    mma_tf32(acc[tm][tn], afr[tm], bfr[tn]);
        }
        __syncthreads();
    }

    // ---- epilogue: each thread owns (r, 2ca), (r, 2ca+1), (r+8, ...) per tile
    float* Ob = Out + (long long)b * obs;
    const float* Rb = Res + (long long)b * obs;
#pragma unroll
    for (int tm = 0; tm < 2; tm++) {
#pragma unroll
        for (int tn = 0; tn < 4; tn++) {
            int col = n0 + wn * 32 + tn * 8 + 2 * ca;
            int r0 = m0 + wm * 32 + tm * 16 + ra;
            int r1 = r0 + 8;
            if (r0 < M) {
                float2 v = make_float2(acc[tm][tn][0], acc[tm][tn][1]);
                long long off = (long long)r0 * HW + col;
                if (addRes) { float2 rr = *(const float2*)&Rb[off]; v.x += rr.x; v.y += rr.y; }
                *(float2*)&Ob[off] = v;
            }
            if (r1 < M) {
                float2 v = make_float2(acc[tm][tn][2], acc[tm][tn][3]);
                long long off = (long long)r1 * HW + col;
                if (addRes) { float2 rr = *(const float2*)&Rb[off]; v.x += rr.x; v.y += rr.y; }
                *(float2*)&Ob[off] = v;
            }
        }
    }
}

// ---------------- depthwise 3x3 for qkv (576 ch) + q/k sumsq partials -----------
__global__ __launch_bounds__(256) void dw_qkv_kernel(const float* __restrict__ in,
                                                     const float* __restrict__ w9,
                                                     float* __restrict__ out) {
    int c = blockIdx.y, b = blockIdx.z;
    long long base = ((long long)b * 576 + c) * HW;
    const float* ib = in + base;
    float w[9];
#pragma unroll
    for (int i = 0; i < 9; i++) w[i] = w9[c * 9 + i];
    int n = blockIdx.x * 256 + threadIdx.x;
    int y = n >> 7, x = n & 127;
    float s = 0.f;
#pragma unroll
    for (int ky = 0; ky < 3; ky++) {
        int iy = y + ky - 1;
        if ((unsigned)iy >= IMG_W) continue;
#pragma unroll
        for (int kx = 0; kx < 3; kx++) {
            int ix = x + kx - 1;
            if ((unsigned)ix >= IMG_W) continue;
            s += w[ky * 3 + kx] * ib[iy * IMG_W + ix];
        }
    }
    out[base + n] = s;
    if (c < 384) {
        __shared__ float red[256];
        red[threadIdx.x] = s * s;
        __syncthreads();
        for (int st = 128; st; st >>= 1) {
            if (threadIdx.x < st) red[threadIdx.x] += red[threadIdx.x + st];
            __syncthreads();
        }
        if (threadIdx.x == 0)
            g_rnpart[(long long)blockIdx.x * (BATCH * 384) + b * 384 + c] = red[0];
    }
}

// ---------------- reduce sumsq partials -> inverse norms ------------------------
__global__ __launch_bounds__(256) void rn_reduce_kernel() {
    int r = blockIdx.x * 256 + threadIdx.x;   // 0..1535
    if (r >= BATCH * 384) return;
    float s = 0.f;
#pragma unroll 8
    for (int p = 0; p < 64; p++) s += g_rnpart[(long long)p * (BATCH * 384) + r];
    g_rn[r] = 1.f / fmaxf(sqrtf(s), 1e-12f);
}

// ---------------- split-K partial Q.K^T -----------------------------------------
__global__ __launch_bounds__(256) void attn_part_kernel() {
    int chunk = blockIdx.x;
    int bh = blockIdx.y;
    int b = bh >> 2, h = bh & 3;
    const float* qb = g_S1 + ((long long)b * 576 + h * DHEAD) * HW;
    const float* kb = g_S1 + ((long long)b * 576 + DIM + h * DHEAD) * HW;
    __shared__ float sq[48][65], sk[48][65];
    int tid = threadIdx.x;
    int tc = tid & 15, tr = tid >> 4;
    int c0 = tr * 3, d0 = tc * 3;
    float acc[3][3] = {};
    long long nbase = (long long)chunk * 1024;
    for (int nn = 0; nn < 1024; nn += 64) {
#pragma unroll
        for (int i = 0; i < 12; i++) {
            int idx = tid + i * 256;
            int r = idx >> 6, col = idx & 63;
            sq[r][col] = qb[(long long)r * HW + nbase + nn + col];
            sk[r][col] = kb[(long long)r * HW + nbase + nn + col];
        }
        __syncthreads();
#pragma unroll
        for (int kk = 0; kk < 64; kk++) {
            float q0 = sq[c0][kk], q1 = sq[c0 + 1][kk], q2 = sq[c0 + 2][kk];
            float k0 = sk[d0][kk], k1 = sk[d0 + 1][kk], k2 = sk[d0 + 2][kk];
            acc[0][0] += q0 * k0; acc[0][1] += q0 * k1; acc[0][2] += q0 * k2;
            acc[1][0] += q1 * k0; acc[1][1] += q1 * k1; acc[1][2] += q1 * k2;
            acc[2][0] += q2 * k0; acc[2][1] += q2 * k1; acc[2][2] += q2 * k2;
        }
        __syncthreads();
    }
    float* P = g_Apart + ((long long)bh * 16 + chunk) * (DHEAD * DHEAD);
#pragma unroll
    for (int i = 0; i < 3; i++)
#pragma unroll
        for (int j = 0; j < 3; j++)
            P[(c0 + i) * DHEAD + d0 + j] = acc[i][j];
}

// ---------------- reduce partials, scale, softmax -------------------------------
__global__ __launch_bounds__(256) void attn_finish_kernel(const float* __restrict__ temp) {
    int bh = blockIdx.x;
    int b = bh >> 2, h = bh & 3;
    __shared__ float sA[DHEAD * DHEAD];
    int tid = threadIdx.x;
    for (int i = tid; i < DHEAD * DHEAD; i += 256) {
        float s = 0.f;
        for (int p = 0; p < 16; p++)
            s += g_Apart[((long long)bh * 16 + p) * (DHEAD * DHEAD) + i];
        int c = i / DHEAD, d = i % DHEAD;
        float scale = g_rn[b * 384 + h * DHEAD + c] *
                      g_rn[b * 384 + DIM + h * DHEAD + d] * temp[h];
        sA[i] = s * scale;
    }
    __syncthreads();
    if (tid < DHEAD) {
        float mx = -1e30f;
        for (int d = 0; d < DHEAD; d++) mx = fmaxf(mx, sA[tid * DHEAD + d]);
        float sum = 0.f;
        for (int d = 0; d < DHEAD; d++) sum += __expf(sA[tid * DHEAD + d] - mx);
        float inv = 1.f / sum;
        for (int d = 0; d < DHEAD; d++)
            g_A[bh * DHEAD * DHEAD + tid * DHEAD + d] =
                __expf(sA[tid * DHEAD + d] - mx) * inv;
    }
}

// ---------------- out = A @ V ---------------------------------------------------
__global__ __launch_bounds__(256) void av_kernel() {
    int bh = blockIdx.y;
    int b = bh >> 2, h = bh & 3;
    __shared__ float sA[DHEAD][DHEAD];
    int tid = threadIdx.x;
    for (int i = tid; i < DHEAD * DHEAD; i += 256)
        sA[i / DHEAD][i % DHEAD] = g_A[bh * DHEAD * DHEAD + i];
    __syncthreads();
    int n = blockIdx.x * 256 + tid;
    const float* vb = g_S1 + ((long long)b * 576 + 2 * DIM + h * DHEAD) * HW + n;
    float v[DHEAD];
#pragma unroll
    for (int d = 0; d < DHEAD; d++) v[d] = vb[(long long)d * HW];
    float* ob = g_S2 + ((long long)b * DIM + h * DHEAD) * HW + n;
#pragma unroll 4
    for (int c = 0; c < DHEAD; c++) {
        float s = 0.f;
#pragma unroll
        for (int d = 0; d < DHEAD; d++) s += sA[c][d] * v[d];
        ob[(long long)c * HW] = s;
    }
}

// ---------------- fused GDFN depthwise 3x3 + GELU gate --------------------------
__global__ __launch_bounds__(256) void dw_gate_kernel(const float* __restrict__ in,
                                                      const float* __restrict__ w9,
                                                      float* __restrict__ out) {
    int c = blockIdx.y, b = blockIdx.z;
    const float* ib1 = in + ((long long)b * 1020 + c) * HW;
    const float* ib2 = in + ((long long)b * 1020 + HIDDEN + c) * HW;
    float w1[9], w2[9];
#pragma unroll
    for (int i = 0; i < 9; i++) { w1[i] = w9[c * 9 + i]; w2[i] = w9[(HIDDEN + c) * 9 + i]; }
    int n = blockIdx.x * 256 + threadIdx.x;
    int y = n >> 7, x = n & 127;
    float s1 = 0.f, s2 = 0.f;
#pragma unroll
    for (int ky = 0; ky < 3; ky++) {
        int iy = y + ky - 1;
        if ((unsigned)iy >= IMG_W) continue;
#pragma unroll
        for (int kx = 0; kx < 3; kx++) {
            int ix = x + kx - 1;
            if ((unsigned)ix >= IMG_W) continue;
            float v1 = ib1[iy * IMG_W + ix];
            float v2 = ib2[iy * IMG_W + ix];
            s1 += w1[ky * 3 + kx] * v1;
            s2 += w2[ky * 3 + kx] * v2;
        }
    }
    float g = 0.5f * s1 * (1.f + erff(s1 * 0.70710678118654752f));
    out[((long long)b * HIDDEN + c) * HW + n] = g * s2;
}

// =============================================================================
extern "C" void kernel_launch(void* const* d_in, const int* in_sizes, int n_in,
                              void* d_out, int out_size) {
    const float* x     = (const float*)d_in[0];
    const float* n1w   = (const float*)d_in[1];
    const float* qkvw  = (const float*)d_in[2];
    const float* qkvdw = (const float*)d_in[3];
    const float* temp  = (const float*)d_in[4];
    const float* projw = (const float*)d_in[5];
    const float* n2w   = (const float*)d_in[6];
    const float* pinw  = (const float*)d_in[7];
    const float* dww   = (const float*)d_in[8];
    const float* poutw = (const float*)d_in[9];
    float* out = (float*)d_out;

    float *S0, *S1, *S2, *Mn, *Is;
    cudaGetSymbolAddress((void**)&S0, g_S0);
    cudaGetSymbolAddress((void**)&S1, g_S1);
    cudaGetSymbolAddress((void**)&S2, g_S2);
    cudaGetSymbolAddress((void**)&Mn, g_mean);
    cudaGetSymbolAddress((void**)&Is, g_istd);

    dim3 pxGrid(HW / 256, BATCH);

    // ---- MDTA branch ----
    ln_stats_kernel<<<pxGrid, 256>>>(x, Mn, Is);

    // qkv 1x1 (LN fused): 576 x 192
    gemm_tc<<<dim3(HW / 128, 9, BATCH), 256>>>(
        qkvw, x, S0, nullptr, Mn, Is, n1w,
        576, DIM, (long long)DIM * HW, (long long)576 * HW, 0);

    dw_qkv_kernel<<<dim3(HW / 256, 576, BATCH), 256>>>(S0, qkvdw, S1);
    rn_reduce_kernel<<<6, 256>>>();
    attn_part_kernel<<<dim3(16, 16), 256>>>();
    attn_finish_kernel<<<16, 256>>>(temp);
    av_kernel<<<dim3(HW / 256, 16), 256>>>();

    // proj 1x1 (192x192) + residual(x) -> d_out
    gemm_tc<<<dim3(HW / 128, 3, BATCH), 256>>>(
        projw, S2, out, x, nullptr, nullptr, nullptr,
        DIM, DIM, (long long)DIM * HW, (long long)DIM * HW, 1);

    // ---- GDFN branch ----
    ln_stats_kernel<<<pxGrid, 256>>>(out, Mn, Is);

    // pin 1x1 (LN fused): 1020 x 192
    gemm_tc<<<dim3(HW / 128, 16, BATCH), 256>>>(
        pinw, out, S0, nullptr, Mn, Is, n2w,
        1020, DIM, (long long)DIM * HW, (long long)1020 * HW, 0);

    dw_gate_kernel<<<dim3(HW / 256, HIDDEN, BATCH), 256>>>(S0, dww, S1);

    // pout 1x1 (192x510) + residual(d_out) -> d_out
    gemm_tc<<<dim3(HW / 128, 3, BATCH), 256>>>(
        poutw, S1, out, out, nullptr, nullptr, nullptr,
        DIM, HIDDEN, (long long)HIDDEN * HW, (long long)DIM * HW, 1);
}

// round 6
// speedup vs baseline: 1.6266x; 1.1443x over previous
#include <cuda_runtime.h>
#include <cuda_bf16.h>
#include <math.h>
#include <stdint.h>

#define HW 16384
#define IMG_W 128
#define DIM 192
#define HEADS 4
#define DHEAD 48
#define HIDDEN 510
#define BATCH 4

// ---------------- scratch (static device arrays; no cudaMalloc allowed) --------
__device__ __nv_bfloat16 g_S0b[BATCH * 1020 * HW]; // conv1x1 outputs (qkv:576 / pin:1020)
__device__ __nv_bfloat16 g_S1b[BATCH * 576 * HW];  // dw outputs (qkv) / gated gdfn (510)
__device__ __nv_bfloat16 g_S2b[BATCH * DIM * HW];  // attention output
__device__ float g_mean[BATCH * HW];
__device__ float g_istd[BATCH * HW];
__device__ float g_rn[BATCH * 2 * DIM];
__device__ float g_rnpart[64 * BATCH * 2 * DIM];   // [p][r]
__device__ float g_A[16 * DHEAD * DHEAD];
__device__ float g_Apart[16 * 16 * DHEAD * DHEAD];

// ---------------- helpers -------------------------------------------------------
__device__ __forceinline__ uint32_t pack_bf16(float x, float y) {
    __nv_bfloat162 h = __float22bfloat162_rn(make_float2(x, y));
    return *(uint32_t*)&h;
}
__device__ __forceinline__ uint32_t sm_addr(const void* p) {
    return (uint32_t)__cvta_generic_to_shared(p);
}
__device__ __forceinline__ void ldsm_x4(uint32_t* r, uint32_t addr) {
    asm volatile("ldmatrix.sync.aligned.m8n8.x4.shared.b16 {%0,%1,%2,%3}, [%4];"
        : "=r"(r[0]), "=r"(r[1]), "=r"(r[2]), "=r"(r[3]) : "r"(addr));
}
__device__ __forceinline__ void ldsm_x2t(uint32_t* r, uint32_t addr) {
    asm volatile("ldmatrix.sync.aligned.m8n8.x2.trans.shared.b16 {%0,%1}, [%2];"
        : "=r"(r[0]), "=r"(r[1]) : "r"(addr));
}
__device__ __forceinline__ void mma_bf16(float* d, const uint32_t* a, const uint32_t* b) {
    asm volatile("mma.sync.aligned.m16n8k16.row.col.f32.bf16.bf16.f32 "
        "{%0,%1,%2,%3}, {%4,%5,%6,%7}, {%8,%9}, {%0,%1,%2,%3};"
        : "+f"(d[0]), "+f"(d[1]), "+f"(d[2]), "+f"(d[3])
        : "r"(a[0]), "r"(a[1]), "r"(a[2]), "r"(a[3]), "r"(b[0]), "r"(b[1]));
}

// ---------------- per-pixel LN stats --------------------------------------------
__global__ __launch_bounds__(256) void ln_stats_kernel(const float* __restrict__ x,
                                                       float* __restrict__ mean,
                                                       float* __restrict__ istd) {
    int n = blockIdx.x * 256 + threadIdx.x;
    int b = blockIdx.y;
    const float* xb = x + (long long)b * DIM * HW + n;
    float s = 0.f, s2 = 0.f;
#pragma unroll 8
    for (int c = 0; c < DIM; c++) {
        float v = xb[(long long)c * HW];
        s += v; s2 += v * v;
    }
    float m = s * (1.f / DIM);
    float var = s2 * (1.f / DIM) - m * m;
    mean[b * HW + n] = m;
    istd[b * HW + n] = rsqrtf(var + 1e-6f);
}

// ---------------- bf16 tensor-core GEMM -----------------------------------------
// Out[b,m,n] = sum_k W[m,k] * Bval[k,n] (+Res).
// inBf16=0: X fp32 + LN fusion (mean/istd/lnW).  inBf16=1: X bf16 raw.
// outBf16=1: write bf16 to Outv.  outBf16=0: fp32 (+Res if addRes).
// BM=64, BN=128, BK=16; 8 warps 2(M)x4(N); warp tile 32x32; mma m16n8k16.
__global__ __launch_bounds__(256) void gemm_bf16(const float* __restrict__ Wm,
                                                 const void* __restrict__ Xv,
                                                 void* __restrict__ Outv,
                                                 const float* __restrict__ Res,
                                                 const float* __restrict__ lnMean,
                                                 const float* __restrict__ lnIstd,
                                                 const float* __restrict__ lnW,
                                                 int M, int K,
                                                 long long xbs, long long obs,
                                                 int inBf16, int outBf16, int addRes) {
    __shared__ __align__(16) __nv_bfloat16 As[64][24];   // [m][k], stride 24 halfs
    __shared__ __align__(16) __nv_bfloat16 Bs[16][136];  // [k][n], stride 136 halfs
    int tid = threadIdx.x;
    int lane = tid & 31, wid = tid >> 5;
    int wm = wid & 1, wn = wid >> 1;
    int ra = lane >> 2, ca = lane & 3;
    int n0 = blockIdx.x * 128;
    int m0 = blockIdx.y * 64;
    int b  = blockIdx.z;

    const float* Xf = (const float*)Xv + (long long)b * xbs;
    const __nv_bfloat16* Xh = (const __nv_bfloat16*)Xv + (long long)b * xbs;
    const float* Mb = lnMean ? lnMean + (long long)b * HW : nullptr;
    const float* Ib = lnMean ? lnIstd + (long long)b * HW : nullptr;

    float acc[2][4][4];
#pragma unroll
    for (int i = 0; i < 2; i++)
#pragma unroll
        for (int j = 0; j < 4; j++)
#pragma unroll
            for (int q = 0; q < 4; q++) acc[i][j][q] = 0.f;

    int am = tid >> 2;             // 0..63
    int ak0 = (tid & 3) * 4;       // 0,4,8,12

    // ldmatrix source addresses (constant across k-loop)
    uint32_t aAddr[2];
#pragma unroll
    for (int tm = 0; tm < 2; tm++)
        aAddr[tm] = sm_addr(&As[wm * 32 + tm * 16 + (lane & 15)][(lane >> 4) * 8]);
    uint32_t bAddr[4];
#pragma unroll
    for (int tn = 0; tn < 4; tn++)
        bAddr[tn] = sm_addr(&Bs[lane & 15][wn * 32 + tn * 8]);

    for (int k0 = 0; k0 < K; k0 += 16) {
        // ---- stage A
        float a_st[4];
#pragma unroll
        for (int j = 0; j < 4; j++) {
            int m = m0 + am, k = k0 + ak0 + j;
            a_st[j] = (m < M && k < K) ? Wm[(long long)m * K + k] : 0.f;
        }
        // ---- stage B
        float4 bf_st[2];
        uint4 bh_st;
        if (!inBf16) {
#pragma unroll
            for (int i = 0; i < 2; i++) {
                int f4 = tid + i * 256;
                int bk = f4 >> 5;
                int bn = (f4 & 31) * 4;
                int k = k0 + bk;
                float4 v = make_float4(0.f, 0.f, 0.f, 0.f);
                if (k < K) {
                    v = *(const float4*)&Xf[(long long)k * HW + n0 + bn];
                    float4 mm = *(const float4*)&Mb[n0 + bn];
                    float4 ii = *(const float4*)&Ib[n0 + bn];
                    float wk = lnW[k];
                    v.x = (v.x - mm.x) * ii.x * wk;
                    v.y = (v.y - mm.y) * ii.y * wk;
                    v.z = (v.z - mm.z) * ii.z * wk;
                    v.w = (v.w - mm.w) * ii.w * wk;
                }
                bf_st[i] = v;
            }
        } else {
            int bk = tid >> 4;
            int bn = (tid & 15) * 8;
            int k = k0 + bk;
            bh_st = make_uint4(0u, 0u, 0u, 0u);
            if (k < K) bh_st = *(const uint4*)&Xh[(long long)k * HW + n0 + bn];
        }
        __syncthreads();
        // ---- store A
        *(uint2*)&As[am][ak0] = make_uint2(pack_bf16(a_st[0], a_st[1]),
                                           pack_bf16(a_st[2], a_st[3]));
        // ---- store B
        if (!inBf16) {
#pragma unroll
            for (int i = 0; i < 2; i++) {
                int f4 = tid + i * 256;
                int bk = f4 >> 5;
                int bn = (f4 & 31) * 4;
                *(uint2*)&Bs[bk][bn] = make_uint2(pack_bf16(bf_st[i].x, bf_st[i].y),
                                                  pack_bf16(bf_st[i].z, bf_st[i].w));
            }
        } else {
            int bk = tid >> 4;
            int bn = (tid & 15) * 8;
            *(uint4*)&Bs[bk][bn] = bh_st;
        }
        __syncthreads();

        // ---- fragments + MMA
        uint32_t afr[2][4], bfr[4][2];
#pragma unroll
        for (int tm = 0; tm < 2; tm++) ldsm_x4(afr[tm], aAddr[tm]);
#pragma unroll
        for (int tn = 0; tn < 4; tn++) ldsm_x2t(bfr[tn], bAddr[tn]);
#pragma unroll
        for (int tm = 0; tm < 2; tm++)
#pragma unroll
            for (int tn = 0; tn < 4; tn++)
                mma_bf16(acc[tm][tn], afr[tm], bfr[tn]);
        __syncthreads();
    }

    // ---- epilogue
    if (outBf16) {
        __nv_bfloat16* Ob = (__nv_bfloat16*)Outv + (long long)b * obs;
#pragma unroll
        for (int tm = 0; tm < 2; tm++)
#pragma unroll
            for (int tn = 0; tn < 4; tn++) {
                int col = n0 + wn * 32 + tn * 8 + 2 * ca;
                int r0 = m0 + wm * 32 + tm * 16 + ra;
                int r1 = r0 + 8;
                if (r0 < M)
                    *(uint32_t*)&Ob[(long long)r0 * HW + col] =
                        pack_bf16(acc[tm][tn][0], acc[tm][tn][1]);
                if (r1 < M)
                    *(uint32_t*)&Ob[(long long)r1 * HW + col] =
                        pack_bf16(acc[tm][tn][2], acc[tm][tn][3]);
            }
    } else {
        float* Ob = (float*)Outv + (long long)b * obs;
        const float* Rb = Res + (long long)b * obs;
#pragma unroll
        for (int tm = 0; tm < 2; tm++)
#pragma unroll
            for (int tn = 0; tn < 4; tn++) {
                int col = n0 + wn * 32 + tn * 8 + 2 * ca;
                int r0 = m0 + wm * 32 + tm * 16 + ra;
                int r1 = r0 + 8;
                if (r0 < M) {
                    float2 v = make_float2(acc[tm][tn][0], acc[tm][tn][1]);
                    long long off = (long long)r0 * HW + col;
                    if (addRes) { float2 rr = *(const float2*)&Rb[off]; v.x += rr.x; v.y += rr.y; }
                    *(float2*)&Ob[off] = v;
                }
                if (r1 < M) {
                    float2 v = make_float2(acc[tm][tn][2], acc[tm][tn][3]);
                    long long off = (long long)r1 * HW + col;
                    if (addRes) { float2 rr = *(const float2*)&Rb[off]; v.x += rr.x; v.y += rr.y; }
                    *(float2*)&Ob[off] = v;
                }
            }
    }
}

// ---------------- depthwise 3x3 qkv (bf16 io) + q/k sumsq partials --------------
__global__ __launch_bounds__(256) void dw_qkv_kernel(const __nv_bfloat16* __restrict__ in,
                                                     const float* __restrict__ w9,
                                                     __nv_bfloat16* __restrict__ out) {
    int c = blockIdx.y, b = blockIdx.z;
    long long base = ((long long)b * 576 + c) * HW;
    const __nv_bfloat16* ib = in + base;
    float w[9];
#pragma unroll
    for (int i = 0; i < 9; i++) w[i] = w9[c * 9 + i];
    int n = blockIdx.x * 256 + threadIdx.x;
    int y = n >> 7, x = n & 127;
    float s = 0.f;
#pragma unroll
    for (int ky = 0; ky < 3; ky++) {
        int iy = y + ky - 1;
        if ((unsigned)iy >= IMG_W) continue;
#pragma unroll
        for (int kx = 0; kx < 3; kx++) {
            int ix = x + kx - 1;
            if ((unsigned)ix >= IMG_W) continue;
            s += w[ky * 3 + kx] * __bfloat162float(ib[iy * IMG_W + ix]);
        }
    }
    out[base + n] = __float2bfloat16(s);
    if (c < 384) {
        __shared__ float red[256];
        red[threadIdx.x] = s * s;
        __syncthreads();
        for (int st = 128; st; st >>= 1) {
            if (threadIdx.x < st) red[threadIdx.x] += red[threadIdx.x + st];
            __syncthreads();
        }
        if (threadIdx.x == 0)
            g_rnpart[(long long)blockIdx.x * (BATCH * 384) + b * 384 + c] = red[0];
    }
}

// ---------------- reduce sumsq partials -> inverse norms ------------------------
__global__ __launch_bounds__(256) void rn_reduce_kernel() {
    int r = blockIdx.x * 256 + threadIdx.x;
    if (r >= BATCH * 384) return;
    float s = 0.f;
#pragma unroll 8
    for (int p = 0; p < 64; p++) s += g_rnpart[(long long)p * (BATCH * 384) + r];
    g_rn[r] = 1.f / fmaxf(sqrtf(s), 1e-12f);
}

// ---------------- split-K partial Q.K^T (bf16 in) -------------------------------
__global__ __launch_bounds__(256) void attn_part_kernel() {
    int chunk = blockIdx.x;
    int bh = blockIdx.y;
    int b = bh >> 2, h = bh & 3;
    const __nv_bfloat16* qb = g_S1b + ((long long)b * 576 + h * DHEAD) * HW;
    const __nv_bfloat16* kb = g_S1b + ((long long)b * 576 + DIM + h * DHEAD) * HW;
    __shared__ float sq[48][65], sk[48][65];
    int tid = threadIdx.x;
    int tc = tid & 15, tr = tid >> 4;
    int c0 = tr * 3, d0 = tc * 3;
    float acc[3][3] = {};
    long long nbase = (long long)chunk * 1024;
    for (int nn = 0; nn < 1024; nn += 64) {
#pragma unroll
        for (int i = 0; i < 6; i++) {
            int idx = tid + i * 256;        // 0..1535 bf16x2 pairs
            int r = idx >> 5, cp = (idx & 31) * 2;
            __nv_bfloat162 q2 = *(const __nv_bfloat162*)&qb[(long long)r * HW + nbase + nn + cp];
            __nv_bfloat162 k2 = *(const __nv_bfloat162*)&kb[(long long)r * HW + nbase + nn + cp];
            sq[r][cp] = __bfloat162float(q2.x); sq[r][cp + 1] = __bfloat162float(q2.y);
            sk[r][cp] = __bfloat162float(k2.x); sk[r][cp + 1] = __bfloat162float(k2.y);
        }
        __syncthreads();
#pragma unroll
        for (int kk = 0; kk < 64; kk++) {
            float q0 = sq[c0][kk], q1 = sq[c0 + 1][kk], q2 = sq[c0 + 2][kk];
            float k0 = sk[d0][kk], k1 = sk[d0 + 1][kk], k2 = sk[d0 + 2][kk];
            acc[0][0] += q0 * k0; acc[0][1] += q0 * k1; acc[0][2] += q0 * k2;
            acc[1][0] += q1 * k0; acc[1][1] += q1 * k1; acc[1][2] += q1 * k2;
            acc[2][0] += q2 * k0; acc[2][1] += q2 * k1; acc[2][2] += q2 * k2;
        }
        __syncthreads();
    }
    float* P = g_Apart + ((long long)bh * 16 + chunk) * (DHEAD * DHEAD);
#pragma unroll
    for (int i = 0; i < 3; i++)
#pragma unroll
        for (int j = 0; j < 3; j++)
            P[(c0 + i) * DHEAD + d0 + j] = acc[i][j];
}

// ---------------- reduce partials, scale, softmax -------------------------------
__global__ __launch_bounds__(256) void attn_finish_kernel(const float* __restrict__ temp) {
    int bh = blockIdx.x;
    int b = bh >> 2, h = bh & 3;
    __shared__ float sA[DHEAD * DHEAD];
    int tid = threadIdx.x;
    for (int i = tid; i < DHEAD * DHEAD; i += 256) {
        float s = 0.f;
        for (int p = 0; p < 16; p++)
            s += g_Apart[((long long)bh * 16 + p) * (DHEAD * DHEAD) + i];
        int c = i / DHEAD, d = i % DHEAD;
        float scale = g_rn[b * 384 + h * DHEAD + c] *
                      g_rn[b * 384 + DIM + h * DHEAD + d] * temp[h];
        sA[i] = s * scale;
    }
    __syncthreads();
    if (tid < DHEAD) {
        float mx = -1e30f;
        for (int d = 0; d < DHEAD; d++) mx = fmaxf(mx, sA[tid * DHEAD + d]);
        float sum = 0.f;
        for (int d = 0; d < DHEAD; d++) sum += __expf(sA[tid * DHEAD + d] - mx);
        float inv = 1.f / sum;
        for (int d = 0; d < DHEAD; d++)
            g_A[bh * DHEAD * DHEAD + tid * DHEAD + d] =
                __expf(sA[tid * DHEAD + d] - mx) * inv;
    }
}

// ---------------- out = A @ V (bf16 io) -----------------------------------------
__global__ __launch_bounds__(256) void av_kernel() {
    int bh = blockIdx.y;
    int b = bh >> 2, h = bh & 3;
    __shared__ float sA[DHEAD][DHEAD];
    int tid = threadIdx.x;
    for (int i = tid; i < DHEAD * DHEAD; i += 256)
        sA[i / DHEAD][i % DHEAD] = g_A[bh * DHEAD * DHEAD + i];
    __syncthreads();
    int n = blockIdx.x * 256 + tid;
    const __nv_bfloat16* vb = g_S1b + ((long long)b * 576 + 2 * DIM + h * DHEAD) * HW + n;
    float v[DHEAD];
#pragma unroll
    for (int d = 0; d < DHEAD; d++) v[d] = __bfloat162float(vb[(long long)d * HW]);
    __nv_bfloat16* ob = g_S2b + ((long long)b * DIM + h * DHEAD) * HW + n;
#pragma unroll 4
    for (int c = 0; c < DHEAD; c++) {
        float s = 0.f;
#pragma unroll
        for (int d = 0; d < DHEAD; d++) s += sA[c][d] * v[d];
        ob[(long long)c * HW] = __float2bfloat16(s);
    }
}

// ---------------- fused GDFN depthwise 3x3 + GELU gate (bf16 io) ----------------
__global__ __launch_bounds__(256) void dw_gate_kernel(const __nv_bfloat16* __restrict__ in,
                                                      const float* __restrict__ w9,
                                                      __nv_bfloat16* __restrict__ out) {
    int c = blockIdx.y, b = blockIdx.z;
    const __nv_bfloat16* ib1 = in + ((long long)b * 1020 + c) * HW;
    const __nv_bfloat16* ib2 = in + ((long long)b * 1020 + HIDDEN + c) * HW;
    float w1[9], w2[9];
#pragma unroll
    for (int i = 0; i < 9; i++) { w1[i] = w9[c * 9 + i]; w2[i] = w9[(HIDDEN + c) * 9 + i]; }
    int n = blockIdx.x * 256 + threadIdx.x;
    int y = n >> 7, x = n & 127;
    float s1 = 0.f, s2 = 0.f;
#pragma unroll
    for (int ky = 0; ky < 3; ky++) {
        int iy = y + ky - 1;
        if ((unsigned)iy >= IMG_W) continue;
#pragma unroll
        for (int kx = 0; kx < 3; kx++) {
            int ix = x + kx - 1;
            if ((unsigned)ix >= IMG_W) continue;
            s1 += w1[ky * 3 + kx] * __bfloat162float(ib1[iy * IMG_W + ix]);
            s2 += w2[ky * 3 + kx] * __bfloat162float(ib2[iy * IMG_W + ix]);
        }
    }
    float g = 0.5f * s1 * (1.f + erff(s1 * 0.70710678118654752f));
    out[((long long)b * HIDDEN + c) * HW + n] = __float2bfloat16(g * s2);
}

// =============================================================================
extern "C" void kernel_launch(void* const* d_in, const int* in_sizes, int n_in,
                              void* d_out, int out_size) {
    const float* x     = (const float*)d_in[0];
    const float* n1w   = (const float*)d_in[1];
    const float* qkvw  = (const float*)d_in[2];
    const float* qkvdw = (const float*)d_in[3];
    const float* temp  = (const float*)d_in[4];
    const float* projw = (const float*)d_in[5];
    const float* n2w   = (const float*)d_in[6];
    const float* pinw  = (const float*)d_in[7];
    const float* dww   = (const float*)d_in[8];
    const float* poutw = (const float*)d_in[9];
    float* out = (float*)d_out;

    __nv_bfloat16 *S0b, *S1b, *S2b;
    float *Mn, *Is;
    cudaGetSymbolAddress((void**)&S0b, g_S0b);
    cudaGetSymbolAddress((void**)&S1b, g_S1b);
    cudaGetSymbolAddress((void**)&S2b, g_S2b);
    cudaGetSymbolAddress((void**)&Mn, g_mean);
    cudaGetSymbolAddress((void**)&Is, g_istd);

    dim3 pxGrid(HW / 256, BATCH);

    // ---- MDTA branch ----
    ln_stats_kernel<<<pxGrid, 256>>>(x, Mn, Is);

    // qkv 1x1 (LN fused): 576x192, fp32 in -> bf16 out
    gemm_bf16<<<dim3(HW / 128, 9, BATCH), 256>>>(
        qkvw, x, S0b, nullptr, Mn, Is, n1w,
        576, DIM, (long long)DIM * HW, (long long)576 * HW, 0, 1, 0);

    dw_qkv_kernel<<<dim3(HW / 256, 576, BATCH), 256>>>(S0b, qkvdw, S1b);
    rn_reduce_kernel<<<6, 256>>>();
    attn_part_kernel<<<dim3(16, 16), 256>>>();
    attn_finish_kernel<<<16, 256>>>(temp);
    av_kernel<<<dim3(HW / 256, 16), 256>>>();

    // proj 1x1 (192x192): bf16 in -> fp32 out + residual(x)
    gemm_bf16<<<dim3(HW / 128, 3, BATCH), 256>>>(
        projw, S2b, out, x, nullptr, nullptr, nullptr,
        DIM, DIM, (long long)DIM * HW, (long long)DIM * HW, 1, 0, 1);

    // ---- GDFN branch ----
    ln_stats_kernel<<<pxGrid, 256>>>(out, Mn, Is);

    // pin 1x1 (LN fused): 1020x192, fp32 in -> bf16 out
    gemm_bf16<<<dim3(HW / 128, 16, BATCH), 256>>>(
        pinw, out, S0b, nullptr, Mn, Is, n2w,
        1020, DIM, (long long)DIM * HW, (long long)1020 * HW, 0, 1, 0);

    dw_gate_kernel<<<dim3(HW / 256, HIDDEN, BATCH), 256>>>(S0b, dww, S1b);

    // pout 1x1 (192x510): bf16 in -> fp32 out + residual(d_out)
    gemm_bf16<<<dim3(HW / 128, 3, BATCH), 256>>>(
        poutw, S1b, out, out, nullptr, nullptr, nullptr,
        DIM, HIDDEN, (long long)HIDDEN * HW, (long long)DIM * HW, 1, 0, 1);
}

// round 7
// speedup vs baseline: 2.2894x; 1.4075x over previous
#include <cuda_runtime.h>
#include <cuda_bf16.h>
#include <math.h>
#include <stdint.h>

#define HW 16384
#define IMG_W 128
#define DIM 192
#define HEADS 4
#define DHEAD 48
#define HIDDEN 510
#define BATCH 4

// ---------------- scratch (static device arrays) --------------------------------
__device__ __nv_bfloat16 g_S0b[BATCH * 1020 * HW]; // conv1x1 outputs (qkv:576 / pin:1020)
__device__ __nv_bfloat16 g_S1b[BATCH * 576 * HW];  // dw qkv out (576) / gated gdfn (512 pad)
__device__ __nv_bfloat16 g_S2b[BATCH * DIM * HW];  // LN-normalized xhat / attn output
__device__ __nv_bfloat16 g_Wqkv[576 * 192];
__device__ __nv_bfloat16 g_Wproj[192 * 192];
__device__ __nv_bfloat16 g_Wpin[1024 * 192];       // padded M 1020->1024
__device__ __nv_bfloat16 g_Wpout[192 * 512];       // padded K 510->512
__device__ float g_rn[BATCH * 2 * DIM];
__device__ float g_rnpart[64 * BATCH * 2 * DIM];   // [p][r]
__device__ float g_A[16 * DHEAD * DHEAD];
__device__ float g_Apart[16 * 16 * DHEAD * DHEAD];

// ---------------- helpers -------------------------------------------------------
__device__ __forceinline__ uint32_t pack_bf16(float x, float y) {
    __nv_bfloat162 h = __float22bfloat162_rn(make_float2(x, y));
    return *(uint32_t*)&h;
}
__device__ __forceinline__ uint32_t sm_addr(const void* p) {
    return (uint32_t)__cvta_generic_to_shared(p);
}
__device__ __forceinline__ void ldsm_x4(uint32_t* r, uint32_t addr) {
    asm volatile("ldmatrix.sync.aligned.m8n8.x4.shared.b16 {%0,%1,%2,%3}, [%4];"
        : "=r"(r[0]), "=r"(r[1]), "=r"(r[2]), "=r"(r[3]) : "r"(addr));
}
__device__ __forceinline__ void ldsm_x2t(uint32_t* r, uint32_t addr) {
    asm volatile("ldmatrix.sync.aligned.m8n8.x2.trans.shared.b16 {%0,%1}, [%2];"
        : "=r"(r[0]), "=r"(r[1]) : "r"(addr));
}
__device__ __forceinline__ void mma_bf16(float* d, const uint32_t* a, const uint32_t* b) {
    asm volatile("mma.sync.aligned.m16n8k16.row.col.f32.bf16.bf16.f32 "
        "{%0,%1,%2,%3}, {%4,%5,%6,%7}, {%8,%9}, {%0,%1,%2,%3};"
        : "+f"(d[0]), "+f"(d[1]), "+f"(d[2]), "+f"(d[3])
        : "r"(a[0]), "r"(a[1]), "r"(a[2]), "r"(a[3]), "r"(b[0]), "r"(b[1]));
}
__device__ __forceinline__ void cpa16(uint32_t dst, const void* src) {
    asm volatile("cp.async.cg.shared.global [%0], [%1], 16;" :: "r"(dst), "l"(src));
}
__device__ __forceinline__ void cpa_commit() { asm volatile("cp.async.commit_group;"); }
template<int N> __device__ __forceinline__ void cpa_wait() {
    asm volatile("cp.async.wait_group %0;" :: "n"(N));
}

// ---------------- weight fp32 -> bf16 with padding ------------------------------
__global__ __launch_bounds__(256) void wconv_kernel(const float* __restrict__ src,
                                                    __nv_bfloat16* __restrict__ dst,
                                                    int M, int K, int Mp, int Kp) {
    int idx = blockIdx.x * 256 + threadIdx.x;
    int tot = Mp * Kp;
    if (idx >= tot) return;
    int m = idx / Kp, k = idx - m * Kp;
    float v = (m < M && k < K) ? src[m * K + k] : 0.f;
    dst[idx] = __float2bfloat16(v);
}

// ---------------- LN: per-pixel stats + write normalized bf16 xhat ---------------
__global__ __launch_bounds__(256) void ln_apply_kernel(const float* __restrict__ x,
                                                       const float* __restrict__ lnW,
                                                       __nv_bfloat16* __restrict__ xh) {
    __shared__ float sw[DIM];
    int tid = threadIdx.x;
    if (tid < DIM) sw[tid] = lnW[tid];
    __syncthreads();
    int n = blockIdx.x * 256 + tid;
    int b = blockIdx.y;
    const float* xb = x + (long long)b * DIM * HW + n;
    float s = 0.f, s2 = 0.f;
#pragma unroll 8
    for (int c = 0; c < DIM; c++) {
        float v = xb[(long long)c * HW];
        s += v; s2 += v * v;
    }
    float m = s * (1.f / DIM);
    float var = s2 * (1.f / DIM) - m * m;
    float inv = rsqrtf(var + 1e-6f);
    __nv_bfloat16* ob = xh + (long long)b * DIM * HW + n;
#pragma unroll 8
    for (int c = 0; c < DIM; c++)
        ob[(long long)c * HW] = __float2bfloat16((xb[(long long)c * HW] - m) * inv * sw[c]);
}

// ---------------- cp.async 2-stage pipelined bf16 GEMM --------------------------
// Out[b,m,n] = sum_k Wb[m,k]*X[k,n] (+Res). K multiple of 32; W padded to grid M.
// BM=64, BN=128, BK=32; 8 warps 2(M)x4(N); warp tile 32x32.
__global__ __launch_bounds__(256) void gemm_pipe(const __nv_bfloat16* __restrict__ Wb,
                                                 const __nv_bfloat16* __restrict__ X,
                                                 void* __restrict__ Outv,
                                                 const float* __restrict__ Res,
                                                 int M, int K,
                                                 long long xbs, long long obs,
                                                 int outBf16, int addRes) {
    __shared__ __align__(16) __nv_bfloat16 As[2][64][40];
    __shared__ __align__(16) __nv_bfloat16 Bs[2][32][136];
    int tid = threadIdx.x;
    int lane = tid & 31, wid = tid >> 5;
    int wm = wid & 1, wn = wid >> 1;
    int ra = lane >> 2, ca = lane & 3;
    int n0 = blockIdx.x * 128;
    int m0 = blockIdx.y * 64;
    int b  = blockIdx.z;
    const __nv_bfloat16* Xb = X + (long long)b * xbs;

    // cp.async tile indices
    int ar = tid >> 2, ac = (tid & 3) * 8;      // A: 64 rows x 4 chunks
    int br = tid >> 4, bc = (tid & 15) * 8;     // B: rows br, br+16

    float acc[2][4][4];
#pragma unroll
    for (int i = 0; i < 2; i++)
#pragma unroll
        for (int j = 0; j < 4; j++)
#pragma unroll
            for (int q = 0; q < 4; q++) acc[i][j][q] = 0.f;

    int nk = K >> 5;

    // prologue: stage 0
    cpa16(sm_addr(&As[0][ar][ac]), &Wb[(long long)(m0 + ar) * K + ac]);
    cpa16(sm_addr(&Bs[0][br][bc]), &Xb[(long long)br * HW + n0 + bc]);
    cpa16(sm_addr(&Bs[0][br + 16][bc]), &Xb[(long long)(br + 16) * HW + n0 + bc]);
    cpa_commit();

    for (int kt = 0; kt < nk; kt++) {
        if (kt + 1 < nk) {
            int s = (kt + 1) & 1;
            int k0 = (kt + 1) << 5;
            cpa16(sm_addr(&As[s][ar][ac]), &Wb[(long long)(m0 + ar) * K + k0 + ac]);
            cpa16(sm_addr(&Bs[s][br][bc]), &Xb[(long long)(k0 + br) * HW + n0 + bc]);
            cpa16(sm_addr(&Bs[s][br + 16][bc]), &Xb[(long long)(k0 + br + 16) * HW + n0 + bc]);
        }
        cpa_commit();
        cpa_wait<1>();
        __syncthreads();
        int s = kt & 1;
#pragma unroll
        for (int ks = 0; ks < 2; ks++) {
            uint32_t afr[2][4], bfr[4][2];
#pragma unroll
            for (int tm = 0; tm < 2; tm++)
                ldsm_x4(afr[tm],
                    sm_addr(&As[s][wm * 32 + tm * 16 + (lane & 15)][ks * 16 + (lane >> 4) * 8]));
#pragma unroll
            for (int tn = 0; tn < 4; tn++)
                ldsm_x2t(bfr[tn],
                    sm_addr(&Bs[s][ks * 16 + (lane & 15)][wn * 32 + tn * 8]));
#pragma unroll
            for (int tm = 0; tm < 2; tm++)
#pragma unroll
                for (int tn = 0; tn < 4; tn++)
                    mma_bf16(acc[tm][tn], afr[tm], bfr[tn]);
        }
        __syncthreads();
    }

    if (outBf16) {
        __nv_bfloat16* Ob = (__nv_bfloat16*)Outv + (long long)b * obs;
#pragma unroll
        for (int tm = 0; tm < 2; tm++)
#pragma unroll
            for (int tn = 0; tn < 4; tn++) {
                int col = n0 + wn * 32 + tn * 8 + 2 * ca;
                int r0 = m0 + wm * 32 + tm * 16 + ra;
                int r1 = r0 + 8;
                if (r0 < M)
                    *(uint32_t*)&Ob[(long long)r0 * HW + col] =
                        pack_bf16(acc[tm][tn][0], acc[tm][tn][1]);
                if (r1 < M)
                    *(uint32_t*)&Ob[(long long)r1 * HW + col] =
                        pack_bf16(acc[tm][tn][2], acc[tm][tn][3]);
            }
    } else {
        float* Ob = (float*)Outv + (long long)b * obs;
        const float* Rb = Res + (long long)b * obs;
#pragma unroll
        for (int tm = 0; tm < 2; tm++)
#pragma unroll
            for (int tn = 0; tn < 4; tn++) {
                int col = n0 + wn * 32 + tn * 8 + 2 * ca;
                int r0 = m0 + wm * 32 + tm * 16 + ra;
                int r1 = r0 + 8;
                if (r0 < M) {
                    float2 v = make_float2(acc[tm][tn][0], acc[tm][tn][1]);
                    long long off = (long long)r0 * HW + col;
                    if (addRes) { float2 rr = *(const float2*)&Rb[off]; v.x += rr.x; v.y += rr.y; }
                    *(float2*)&Ob[off] = v;
                }
                if (r1 < M) {
                    float2 v = make_float2(acc[tm][tn][2], acc[tm][tn][3]);
                    long long off = (long long)r1 * HW + col;
                    if (addRes) { float2 rr = *(const float2*)&Rb[off]; v.x += rr.x; v.y += rr.y; }
                    *(float2*)&Ob[off] = v;
                }
            }
    }
}

// ---------------- depthwise 3x3 qkv (bf16 io) + q/k sumsq partials --------------
__global__ __launch_bounds__(256) void dw_qkv_kernel(const __nv_bfloat16* __restrict__ in,
                                                     const float* __restrict__ w9,
                                                     __nv_bfloat16* __restrict__ out) {
    int c = blockIdx.y, b = blockIdx.z;
    long long base = ((long long)b * 576 + c) * HW;
    const __nv_bfloat16* ib = in + base;
    float w[9];
#pragma unroll
    for (int i = 0; i < 9; i++) w[i] = w9[c * 9 + i];
    int n = blockIdx.x * 256 + threadIdx.x;
    int y = n >> 7, x = n & 127;
    float s = 0.f;
#pragma unroll
    for (int ky = 0; ky < 3; ky++) {
        int iy = y + ky - 1;
        if ((unsigned)iy >= IMG_W) continue;
#pragma unroll
        for (int kx = 0; kx < 3; kx++) {
            int ix = x + kx - 1;
            if ((unsigned)ix >= IMG_W) continue;
            s += w[ky * 3 + kx] * __bfloat162float(ib[iy * IMG_W + ix]);
        }
    }
    out[base + n] = __float2bfloat16(s);
    if (c < 384) {
        __shared__ float red[256];
        red[threadIdx.x] = s * s;
        __syncthreads();
        for (int st = 128; st; st >>= 1) {
            if (threadIdx.x < st) red[threadIdx.x] += red[threadIdx.x + st];
            __syncthreads();
        }
        if (threadIdx.x == 0)
            g_rnpart[(long long)blockIdx.x * (BATCH * 384) + b * 384 + c] = red[0];
    }
}

// ---------------- reduce sumsq partials -> inverse norms ------------------------
__global__ __launch_bounds__(256) void rn_reduce_kernel() {
    int r = blockIdx.x * 256 + threadIdx.x;
    if (r >= BATCH * 384) return;
    float s = 0.f;
#pragma unroll 8
    for (int p = 0; p < 64; p++) s += g_rnpart[(long long)p * (BATCH * 384) + r];
    g_rn[r] = 1.f / fmaxf(sqrtf(s), 1e-12f);
}

// ---------------- split-K partial Q.K^T (bf16 in) -------------------------------
__global__ __launch_bounds__(256) void attn_part_kernel() {
    int chunk = blockIdx.x;
    int bh = blockIdx.y;
    int b = bh >> 2, h = bh & 3;
    const __nv_bfloat16* qb = g_S1b + ((long long)b * 576 + h * DHEAD) * HW;
    const __nv_bfloat16* kb = g_S1b + ((long long)b * 576 + DIM + h * DHEAD) * HW;
    __shared__ float sq[48][65], sk[48][65];
    int tid = threadIdx.x;
    int tc = tid & 15, tr = tid >> 4;
    int c0 = tr * 3, d0 = tc * 3;
    float acc[3][3] = {};
    long long nbase = (long long)chunk * 1024;
    for (int nn = 0; nn < 1024; nn += 64) {
#pragma unroll
        for (int i = 0; i < 6; i++) {
            int idx = tid + i * 256;
            int r = idx >> 5, cp = (idx & 31) * 2;
            __nv_bfloat162 q2 = *(const __nv_bfloat162*)&qb[(long long)r * HW + nbase + nn + cp];
            __nv_bfloat162 k2 = *(const __nv_bfloat162*)&kb[(long long)r * HW + nbase + nn + cp];
            sq[r][cp] = __bfloat162float(q2.x); sq[r][cp + 1] = __bfloat162float(q2.y);
            sk[r][cp] = __bfloat162float(k2.x); sk[r][cp + 1] = __bfloat162float(k2.y);
        }
        __syncthreads();
#pragma unroll
        for (int kk = 0; kk < 64; kk++) {
            float q0 = sq[c0][kk], q1 = sq[c0 + 1][kk], q2 = sq[c0 + 2][kk];
            float k0 = sk[d0][kk], k1 = sk[d0 + 1][kk], k2 = sk[d0 + 2][kk];
            acc[0][0] += q0 * k0; acc[0][1] += q0 * k1; acc[0][2] += q0 * k2;
            acc[1][0] += q1 * k0; acc[1][1] += q1 * k1; acc[1][2] += q1 * k2;
            acc[2][0] += q2 * k0; acc[2][1] += q2 * k1; acc[2][2] += q2 * k2;
        }
        __syncthreads();
    }
    float* P = g_Apart + ((long long)bh * 16 + chunk) * (DHEAD * DHEAD);
#pragma unroll
    for (int i = 0; i < 3; i++)
#pragma unroll
        for (int j = 0; j < 3; j++)
            P[(c0 + i) * DHEAD + d0 + j] = acc[i][j];
}

// ---------------- reduce partials, scale, softmax -------------------------------
__global__ __launch_bounds__(256) void attn_finish_kernel(const float* __restrict__ temp) {
    int bh = blockIdx.x;
    int b = bh >> 2, h = bh & 3;
    __shared__ float sA[DHEAD * DHEAD];
    int tid = threadIdx.x;
    for (int i = tid; i < DHEAD * DHEAD; i += 256) {
        float s = 0.f;
        for (int p = 0; p < 16; p++)
            s += g_Apart[((long long)bh * 16 + p) * (DHEAD * DHEAD) + i];
        int c = i / DHEAD, d = i % DHEAD;
        float scale = g_rn[b * 384 + h * DHEAD + c] *
                      g_rn[b * 384 + DIM + h * DHEAD + d] * temp[h];
        sA[i] = s * scale;
    }
    __syncthreads();
    if (tid < DHEAD) {
        float mx = -1e30f;
        for (int d = 0; d < DHEAD; d++) mx = fmaxf(mx, sA[tid * DHEAD + d]);
        float sum = 0.f;
        for (int d = 0; d < DHEAD; d++) sum += __expf(sA[tid * DHEAD + d] - mx);
        float inv = 1.f / sum;
        for (int d = 0; d < DHEAD; d++)
            g_A[bh * DHEAD * DHEAD + tid * DHEAD + d] =
                __expf(sA[tid * DHEAD + d] - mx) * inv;
    }
}

// ---------------- out = A @ V (bf16 io) -----------------------------------------
__global__ __launch_bounds__(256) void av_kernel() {
    int bh = blockIdx.y;
    int b = bh >> 2, h = bh & 3;
    __shared__ float sA[DHEAD][DHEAD];
    int tid = threadIdx.x;
    for (int i = tid; i < DHEAD * DHEAD; i += 256)
        sA[i / DHEAD][i % DHEAD] = g_A[bh * DHEAD * DHEAD + i];
    __syncthreads();
    int n = blockIdx.x * 256 + tid;
    const __nv_bfloat16* vb = g_S1b + ((long long)b * 576 + 2 * DIM + h * DHEAD) * HW + n;
    float v[DHEAD];
#pragma unroll
    for (int d = 0; d < DHEAD; d++) v[d] = __bfloat162float(vb[(long long)d * HW]);
    __nv_bfloat16* ob = g_S2b + ((long long)b * DIM + h * DHEAD) * HW + n;
#pragma unroll 4
    for (int c = 0; c < DHEAD; c++) {
        float s = 0.f;
#pragma unroll
        for (int d = 0; d < DHEAD; d++) s += sA[c][d] * v[d];
        ob[(long long)c * HW] = __float2bfloat16(s);
    }
}

// ---------------- fused GDFN depthwise 3x3 + GELU gate (bf16 io, 512-pad out) ---
__global__ __launch_bounds__(256) void dw_gate_kernel(const __nv_bfloat16* __restrict__ in,
                                                      const float* __restrict__ w9,
                                                      __nv_bfloat16* __restrict__ out) {
    int c = blockIdx.y, b = blockIdx.z;
    int n = blockIdx.x * 256 + threadIdx.x;
    if (c >= HIDDEN) {            // pad channels 510,511 -> zero
        out[((long long)b * 512 + c) * HW + n] = __float2bfloat16(0.f);
        return;
    }
    const __nv_bfloat16* ib1 = in + ((long long)b * 1020 + c) * HW;
    const __nv_bfloat16* ib2 = in + ((long long)b * 1020 + HIDDEN + c) * HW;
    float w1[9], w2[9];
#pragma unroll
    for (int i = 0; i < 9; i++) { w1[i] = w9[c * 9 + i]; w2[i] = w9[(HIDDEN + c) * 9 + i]; }
    int y = n >> 7, x = n & 127;
    float s1 = 0.f, s2 = 0.f;
#pragma unroll
    for (int ky = 0; ky < 3; ky++) {
        int iy = y + ky - 1;
        if ((unsigned)iy >= IMG_W) continue;
#pragma unroll
        for (int kx = 0; kx < 3; kx++) {
            int ix = x + kx - 1;
            if ((unsigned)ix >= IMG_W) continue;
            s1 += w1[ky * 3 + kx] * __bfloat162float(ib1[iy * IMG_W + ix]);
            s2 += w2[ky * 3 + kx] * __bfloat162float(ib2[iy * IMG_W + ix]);
        }
    }
    float g = 0.5f * s1 * (1.f + erff(s1 * 0.70710678118654752f));
    out[((long long)b * 512 + c) * HW + n] = __float2bfloat16(g * s2);
}

// =============================================================================
extern "C" void kernel_launch(void* const* d_in, const int* in_sizes, int n_in,
                              void* d_out, int out_size) {
    const float* x     = (const float*)d_in[0];
    const float* n1w   = (const float*)d_in[1];
    const float* qkvw  = (const float*)d_in[2];
    const float* qkvdw = (const float*)d_in[3];
    const float* temp  = (const float*)d_in[4];
    const float* projw = (const float*)d_in[5];
    const float* n2w   = (const float*)d_in[6];
    const float* pinw  = (const float*)d_in[7];
    const float* dww   = (const float*)d_in[8];
    const float* poutw = (const float*)d_in[9];
    float* out = (float*)d_out;

    __nv_bfloat16 *S0b, *S1b, *S2b, *Wqkv, *Wproj, *Wpin, *Wpout;
    cudaGetSymbolAddress((void**)&S0b, g_S0b);
    cudaGetSymbolAddress((void**)&S1b, g_S1b);
    cudaGetSymbolAddress((void**)&S2b, g_S2b);
    cudaGetSymbolAddress((void**)&Wqkv, g_Wqkv);
    cudaGetSymbolAddress((void**)&Wproj, g_Wproj);
    cudaGetSymbolAddress((void**)&Wpin, g_Wpin);
    cudaGetSymbolAddress((void**)&Wpout, g_Wpout);

    dim3 pxGrid(HW / 256, BATCH);

    // weight conversions (tiny)
    wconv_kernel<<<(576 * 192 + 255) / 256, 256>>>(qkvw, Wqkv, 576, 192, 576, 192);
    wconv_kernel<<<(192 * 192 + 255) / 256, 256>>>(projw, Wproj, 192, 192, 192, 192);
    wconv_kernel<<<(1024 * 192 + 255) / 256, 256>>>(pinw, Wpin, 1020, 192, 1024, 192);
    wconv_kernel<<<(192 * 512 + 255) / 256, 256>>>(poutw, Wpout, 192, 510, 192, 512);

    // ---- MDTA branch ----
    ln_apply_kernel<<<pxGrid, 256>>>(x, n1w, S2b);

    // qkv 1x1: 576x192, bf16 -> bf16
    gemm_pipe<<<dim3(HW / 128, 9, BATCH), 256>>>(
        Wqkv, S2b, S0b, nullptr, 576, 192, (long long)DIM * HW, (long long)576 * HW, 1, 0);

    dw_qkv_kernel<<<dim3(HW / 256, 576, BATCH), 256>>>(S0b, qkvdw, S1b);
    rn_reduce_kernel<<<6, 256>>>();
    attn_part_kernel<<<dim3(16, 16), 256>>>();
    attn_finish_kernel<<<16, 256>>>(temp);
    av_kernel<<<dim3(HW / 256, 16), 256>>>();

    // proj 1x1 (192x192): bf16 -> fp32 + residual(x)
    gemm_pipe<<<dim3(HW / 128, 3, BATCH), 256>>>(
        Wproj, S2b, out, x, 192, 192, (long long)DIM * HW, (long long)DIM * HW, 0, 1);

    // ---- GDFN branch ----
    ln_apply_kernel<<<pxGrid, 256>>>(out, n2w, S2b);

    // pin 1x1 (1020x192 padded to 1024): bf16 -> bf16
    gemm_pipe<<<dim3(HW / 128, 16, BATCH), 256>>>(
        Wpin, S2b, S0b, nullptr, 1020, 192, (long long)DIM * HW, (long long)1020 * HW, 1, 0);

    dw_gate_kernel<<<dim3(HW / 256, 512, BATCH), 256>>>(S0b, dww, S1b);

    // pout 1x1 (192x512 padded K): bf16 -> fp32 + residual(d_out)
    gemm_pipe<<<dim3(HW / 128, 3, BATCH), 256>>>(
        Wpout, S1b, out, out, 192, 512, (long long)512 * HW, (long long)DIM * HW, 0, 1);
}

// round 8
// speedup vs baseline: 2.3040x; 1.0064x over previous
#include <cuda_runtime.h>
#include <cuda_bf16.h>
#include <math.h>
#include <stdint.h>

#define HW 16384
#define IMG_W 128
#define DIM 192
#define HEADS 4
#define DHEAD 48
#define HIDDEN 510
#define BATCH 4

// ---------------- scratch (static device arrays) --------------------------------
__device__ __nv_bfloat16 g_S0b[BATCH * 1020 * HW]; // conv1x1 outputs (qkv:576 / pin:1020)
__device__ __nv_bfloat16 g_S1b[BATCH * 576 * HW];  // dw qkv out (576) / gated gdfn (512 pad)
__device__ __nv_bfloat16 g_S2b[BATCH * DIM * HW];  // LN-normalized xhat / attn output
__device__ __nv_bfloat16 g_Wqkv[576 * 192];
__device__ __nv_bfloat16 g_Wproj[192 * 192];
__device__ __nv_bfloat16 g_Wpin[1024 * 192];       // padded M 1020->1024
__device__ __nv_bfloat16 g_Wpout[192 * 512];       // padded K 510->512
__device__ float g_rnpart[64 * BATCH * 2 * DIM];   // [p][r]
__device__ float g_A[16 * DHEAD * DHEAD];
__device__ float g_Apart[16 * 16 * DHEAD * DHEAD];

// ---------------- helpers -------------------------------------------------------
__device__ __forceinline__ uint32_t pack_bf16(float x, float y) {
    __nv_bfloat162 h = __float22bfloat162_rn(make_float2(x, y));
    return *(uint32_t*)&h;
}
__device__ __forceinline__ uint32_t sm_addr(const void* p) {
    return (uint32_t)__cvta_generic_to_shared(p);
}
__device__ __forceinline__ void ldsm_x4(uint32_t* r, uint32_t addr) {
    asm volatile("ldmatrix.sync.aligned.m8n8.x4.shared.b16 {%0,%1,%2,%3}, [%4];"
        : "=r"(r[0]), "=r"(r[1]), "=r"(r[2]), "=r"(r[3]) : "r"(addr));
}
__device__ __forceinline__ void ldsm_x2t(uint32_t* r, uint32_t addr) {
    asm volatile("ldmatrix.sync.aligned.m8n8.x2.trans.shared.b16 {%0,%1}, [%2];"
        : "=r"(r[0]), "=r"(r[1]) : "r"(addr));
}
__device__ __forceinline__ void mma_bf16(float* d, const uint32_t* a, const uint32_t* b) {
    asm volatile("mma.sync.aligned.m16n8k16.row.col.f32.bf16.bf16.f32 "
        "{%0,%1,%2,%3}, {%4,%5,%6,%7}, {%8,%9}, {%0,%1,%2,%3};"
        : "+f"(d[0]), "+f"(d[1]), "+f"(d[2]), "+f"(d[3])
        : "r"(a[0]), "r"(a[1]), "r"(a[2]), "r"(a[3]), "r"(b[0]), "r"(b[1]));
}
__device__ __forceinline__ void cpa16(uint32_t dst, const void* src) {
    asm volatile("cp.async.cg.shared.global [%0], [%1], 16;" :: "r"(dst), "l"(src));
}
__device__ __forceinline__ void cpa_commit() { asm volatile("cp.async.commit_group;"); }
template<int N> __device__ __forceinline__ void cpa_wait() {
    asm volatile("cp.async.wait_group %0;" :: "n"(N));
}

// ---------------- weight fp32 -> bf16 with padding ------------------------------
__global__ __launch_bounds__(256) void wconv_kernel(const float* __restrict__ src,
                                                    __nv_bfloat16* __restrict__ dst,
                                                    int M, int K, int Mp, int Kp) {
    int idx = blockIdx.x * 256 + threadIdx.x;
    int tot = Mp * Kp;
    if (idx >= tot) return;
    int m = idx / Kp, k = idx - m * Kp;
    float v = (m < M && k < K) ? src[m * K + k] : 0.f;
    dst[idx] = __float2bfloat16(v);
}

// ---------------- LN: per-pixel stats + write normalized bf16 xhat ---------------
__global__ __launch_bounds__(256) void ln_apply_kernel(const float* __restrict__ x,
                                                       const float* __restrict__ lnW,
                                                       __nv_bfloat16* __restrict__ xh) {
    __shared__ float sw[DIM];
    int tid = threadIdx.x;
    if (tid < DIM) sw[tid] = lnW[tid];
    __syncthreads();
    int n = blockIdx.x * 256 + tid;
    int b = blockIdx.y;
    const float* xb = x + (long long)b * DIM * HW + n;
    float s = 0.f, s2 = 0.f;
#pragma unroll 8
    for (int c = 0; c < DIM; c++) {
        float v = xb[(long long)c * HW];
        s += v; s2 += v * v;
    }
    float m = s * (1.f / DIM);
    float var = s2 * (1.f / DIM) - m * m;
    float inv = rsqrtf(var + 1e-6f);
    __nv_bfloat16* ob = xh + (long long)b * DIM * HW + n;
#pragma unroll 8
    for (int c = 0; c < DIM; c++)
        ob[(long long)c * HW] = __float2bfloat16((xb[(long long)c * HW] - m) * inv * sw[c]);
}

// ---------------- cp.async pipelined bf16 GEMM v3 --------------------------------
// Out[b,m,n] = sum_k Wb[m,k]*X[k,n] (+Res). K multiple of 32; W padded in M.
// BM=64, BN=256, BK=32; 8 warps, each owns full-M 64 x 32-col slice.
__global__ __launch_bounds__(256) void gemm_pipe(const __nv_bfloat16* __restrict__ Wb,
                                                 const __nv_bfloat16* __restrict__ X,
                                                 void* __restrict__ Outv,
                                                 const float* __restrict__ Res,
                                                 int M, int K,
                                                 long long xbs, long long obs,
                                                 int outBf16, int addRes) {
    __shared__ __align__(16) __nv_bfloat16 As[2][64][40];
    __shared__ __align__(16) __nv_bfloat16 Bs[2][32][264];
    int tid = threadIdx.x;
    int lane = tid & 31, wn = tid >> 5;
    int ra = lane >> 2, ca = lane & 3;
    int n0 = blockIdx.x * 256;
    int m0 = blockIdx.y * 64;
    int b  = blockIdx.z;
    const __nv_bfloat16* Xb = X + (long long)b * xbs;

    int ar = tid >> 2, ac = (tid & 3) * 8;      // A: 64 rows x 4 chunks of 8

    float acc[4][4][4];
#pragma unroll
    for (int i = 0; i < 4; i++)
#pragma unroll
        for (int j = 0; j < 4; j++)
#pragma unroll
            for (int q = 0; q < 4; q++) acc[i][j][q] = 0.f;

    int nk = K >> 5;

    // prologue: stage 0
    cpa16(sm_addr(&As[0][ar][ac]), &Wb[(long long)(m0 + ar) * K + ac]);
#pragma unroll
    for (int i = 0; i < 4; i++) {
        int chunk = tid + i * 256;
        int brow = chunk >> 5, bcol = (chunk & 31) * 8;
        cpa16(sm_addr(&Bs[0][brow][bcol]), &Xb[(long long)brow * HW + n0 + bcol]);
    }
    cpa_commit();

    for (int kt = 0; kt < nk; kt++) {
        if (kt + 1 < nk) {
            int s = (kt + 1) & 1;
            int k0 = (kt + 1) << 5;
            cpa16(sm_addr(&As[s][ar][ac]), &Wb[(long long)(m0 + ar) * K + k0 + ac]);
#pragma unroll
            for (int i = 0; i < 4; i++) {
                int chunk = tid + i * 256;
                int brow = chunk >> 5, bcol = (chunk & 31) * 8;
                cpa16(sm_addr(&Bs[s][brow][bcol]), &Xb[(long long)(k0 + brow) * HW + n0 + bcol]);
            }
        }
        cpa_commit();
        cpa_wait<1>();
        __syncthreads();
        int s = kt & 1;
#pragma unroll
        for (int ks = 0; ks < 2; ks++) {
            uint32_t afr[4][4], bfr[4][2];
#pragma unroll
            for (int tm = 0; tm < 4; tm++)
                ldsm_x4(afr[tm],
                    sm_addr(&As[s][tm * 16 + (lane & 15)][ks * 16 + (lane >> 4) * 8]));
#pragma unroll
            for (int tn = 0; tn < 4; tn++)
                ldsm_x2t(bfr[tn],
                    sm_addr(&Bs[s][ks * 16 + (lane & 15)][wn * 32 + tn * 8]));
#pragma unroll
            for (int tm = 0; tm < 4; tm++)
#pragma unroll
                for (int tn = 0; tn < 4; tn++)
                    mma_bf16(acc[tm][tn], afr[tm], bfr[tn]);
        }
        __syncthreads();
    }

    if (outBf16) {
        __nv_bfloat16* Ob = (__nv_bfloat16*)Outv + (long long)b * obs;
#pragma unroll
        for (int tm = 0; tm < 4; tm++)
#pragma unroll
            for (int tn = 0; tn < 4; tn++) {
                int col = n0 + wn * 32 + tn * 8 + 2 * ca;
                int r0 = m0 + tm * 16 + ra;
                int r1 = r0 + 8;
                if (r0 < M)
                    *(uint32_t*)&Ob[(long long)r0 * HW + col] =
                        pack_bf16(acc[tm][tn][0], acc[tm][tn][1]);
                if (r1 < M)
                    *(uint32_t*)&Ob[(long long)r1 * HW + col] =
                        pack_bf16(acc[tm][tn][2], acc[tm][tn][3]);
            }
    } else {
        float* Ob = (float*)Outv + (long long)b * obs;
        const float* Rb = Res + (long long)b * obs;
#pragma unroll
        for (int tm = 0; tm < 4; tm++)
#pragma unroll
            for (int tn = 0; tn < 4; tn++) {
                int col = n0 + wn * 32 + tn * 8 + 2 * ca;
                int r0 = m0 + tm * 16 + ra;
                int r1 = r0 + 8;
                if (r0 < M) {
                    float2 v = make_float2(acc[tm][tn][0], acc[tm][tn][1]);
                    long long off = (long long)r0 * HW + col;
                    if (addRes) { float2 rr = *(const float2*)&Rb[off]; v.x += rr.x; v.y += rr.y; }
                    *(float2*)&Ob[off] = v;
                }
                if (r1 < M) {
                    float2 v = make_float2(acc[tm][tn][2], acc[tm][tn][3]);
                    long long off = (long long)r1 * HW + col;
                    if (addRes) { float2 rr = *(const float2*)&Rb[off]; v.x += rr.x; v.y += rr.y; }
                    *(float2*)&Ob[off] = v;
                }
            }
    }
}

// ---------------- depthwise 3x3 qkv (bf16 io) + q/k sumsq partials --------------
__global__ __launch_bounds__(256) void dw_qkv_kernel(const __nv_bfloat16* __restrict__ in,
                                                     const float* __restrict__ w9,
                                                     __nv_bfloat16* __restrict__ out) {
    int c = blockIdx.y, b = blockIdx.z;
    long long base = ((long long)b * 576 + c) * HW;
    const __nv_bfloat16* ib = in + base;
    float w[9];
#pragma unroll
    for (int i = 0; i < 9; i++) w[i] = w9[c * 9 + i];
    int n = blockIdx.x * 256 + threadIdx.x;
    int y = n >> 7, x = n & 127;
    float s = 0.f;
#pragma unroll
    for (int ky = 0; ky < 3; ky++) {
        int iy = y + ky - 1;
        if ((unsigned)iy >= IMG_W) continue;
#pragma unroll
        for (int kx = 0; kx < 3; kx++) {
            int ix = x + kx - 1;
            if ((unsigned)ix >= IMG_W) continue;
            s += w[ky * 3 + kx] * __bfloat162float(ib[iy * IMG_W + ix]);
        }
    }
    out[base + n] = __float2bfloat16(s);
    if (c < 384) {
        __shared__ float red[256];
        red[threadIdx.x] = s * s;
        __syncthreads();
        for (int st = 128; st; st >>= 1) {
            if (threadIdx.x < st) red[threadIdx.x] += red[threadIdx.x + st];
            __syncthreads();
        }
        if (threadIdx.x == 0)
            g_rnpart[(long long)blockIdx.x * (BATCH * 384) + b * 384 + c] = red[0];
    }
}

// ---------------- split-K partial Q.K^T (bf16 in) -------------------------------
__global__ __launch_bounds__(256) void attn_part_kernel() {
    int chunk = blockIdx.x;
    int bh = blockIdx.y;
    int b = bh >> 2, h = bh & 3;
    const __nv_bfloat16* qb = g_S1b + ((long long)b * 576 + h * DHEAD) * HW;
    const __nv_bfloat16* kb = g_S1b + ((long long)b * 576 + DIM + h * DHEAD) * HW;
    __shared__ float sq[48][65], sk[48][65];
    int tid = threadIdx.x;
    int tc = tid & 15, tr = tid >> 4;
    int c0 = tr * 3, d0 = tc * 3;
    float acc[3][3] = {};
    long long nbase = (long long)chunk * 1024;
    for (int nn = 0; nn < 1024; nn += 64) {
#pragma unroll
        for (int i = 0; i < 6; i++) {
            int idx = tid + i * 256;
            int r = idx >> 5, cp = (idx & 31) * 2;
            __nv_bfloat162 q2 = *(const __nv_bfloat162*)&qb[(long long)r * HW + nbase + nn + cp];
            __nv_bfloat162 k2 = *(const __nv_bfloat162*)&kb[(long long)r * HW + nbase + nn + cp];
            sq[r][cp] = __bfloat162float(q2.x); sq[r][cp + 1] = __bfloat162float(q2.y);
            sk[r][cp] = __bfloat162float(k2.x); sk[r][cp + 1] = __bfloat162float(k2.y);
        }
        __syncthreads();
#pragma unroll
        for (int kk = 0; kk < 64; kk++) {
            float q0 = sq[c0][kk], q1 = sq[c0 + 1][kk], q2 = sq[c0 + 2][kk];
            float k0 = sk[d0][kk], k1 = sk[d0 + 1][kk], k2 = sk[d0 + 2][kk];
            acc[0][0] += q0 * k0; acc[0][1] += q0 * k1; acc[0][2] += q0 * k2;
            acc[1][0] += q1 * k0; acc[1][1] += q1 * k1; acc[1][2] += q1 * k2;
            acc[2][0] += q2 * k0; acc[2][1] += q2 * k1; acc[2][2] += q2 * k2;
        }
        __syncthreads();
    }
    float* P = g_Apart + ((long long)bh * 16 + chunk) * (DHEAD * DHEAD);
#pragma unroll
    for (int i = 0; i < 3; i++)
#pragma unroll
        for (int j = 0; j < 3; j++)
            P[(c0 + i) * DHEAD + d0 + j] = acc[i][j];
}

// ---------------- reduce partials + rownorms, scale, softmax --------------------
__global__ __launch_bounds__(256) void attn_finish_kernel(const float* __restrict__ temp) {
    int bh = blockIdx.x;
    int b = bh >> 2, h = bh & 3;
    __shared__ float sA[DHEAD * DHEAD];
    __shared__ float srn_q[DHEAD], srn_k[DHEAD];
    int tid = threadIdx.x;
    if (tid < 96) {                         // fold rn_reduce: 96 rows x 64 partials
        int i = tid;
        int isK = (i >= DHEAD);
        int cc = i - isK * DHEAD;
        int row = b * 384 + isK * DIM + h * DHEAD + cc;
        float s = 0.f;
#pragma unroll 8
        for (int p = 0; p < 64; p++) s += g_rnpart[(long long)p * (BATCH * 384) + row];
        float v = 1.f / fmaxf(sqrtf(s), 1e-12f);
        if (isK) srn_k[cc] = v; else srn_q[cc] = v;
    }
    __syncthreads();
    for (int i = tid; i < DHEAD * DHEAD; i += 256) {
        float s = 0.f;
        for (int p = 0; p < 16; p++)
            s += g_Apart[((long long)bh * 16 + p) * (DHEAD * DHEAD) + i];
        int c = i / DHEAD, d = i % DHEAD;
        sA[i] = s * srn_q[c] * srn_k[d] * temp[h];
    }
    __syncthreads();
    if (tid < DHEAD) {
        float mx = -1e30f;
        for (int d = 0; d < DHEAD; d++) mx = fmaxf(mx, sA[tid * DHEAD + d]);
        float sum = 0.f;
        for (int d = 0; d < DHEAD; d++) sum += __expf(sA[tid * DHEAD + d] - mx);
        float inv = 1.f / sum;
        for (int d = 0; d < DHEAD; d++)
            g_A[bh * DHEAD * DHEAD + tid * DHEAD + d] =
                __expf(sA[tid * DHEAD + d] - mx) * inv;
    }
}

// ---------------- out = A @ V (bf16 io) -----------------------------------------
__global__ __launch_bounds__(256) void av_kernel() {
    int bh = blockIdx.y;
    int b = bh >> 2, h = bh & 3;
    __shared__ float sA[DHEAD][DHEAD];
    int tid = threadIdx.x;
    for (int i = tid; i < DHEAD * DHEAD; i += 256)
        sA[i / DHEAD][i % DHEAD] = g_A[bh * DHEAD * DHEAD + i];
    __syncthreads();
    int n = blockIdx.x * 256 + tid;
    const __nv_bfloat16* vb = g_S1b + ((long long)b * 576 + 2 * DIM + h * DHEAD) * HW + n;
    float v[DHEAD];
#pragma unroll
    for (int d = 0; d < DHEAD; d++) v[d] = __bfloat162float(vb[(long long)d * HW]);
    __nv_bfloat16* ob = g_S2b + ((long long)b * DIM + h * DHEAD) * HW + n;
#pragma unroll 4
    for (int c = 0; c < DHEAD; c++) {
        float s = 0.f;
#pragma unroll
        for (int d = 0; d < DHEAD; d++) s += sA[c][d] * v[d];
        ob[(long long)c * HW] = __float2bfloat16(s);
    }
}

// ---------------- fused GDFN depthwise 3x3 + GELU gate (bf16 io, 512-pad out) ---
__global__ __launch_bounds__(256) void dw_gate_kernel(const __nv_bfloat16* __restrict__ in,
                                                      const float* __restrict__ w9,
                                                      __nv_bfloat16* __restrict__ out) {
    int c = blockIdx.y, b = blockIdx.z;
    int n = blockIdx.x * 256 + threadIdx.x;
    if (c >= HIDDEN) {
        out[((long long)b * 512 + c) * HW + n] = __float2bfloat16(0.f);
        return;
    }
    const __nv_bfloat16* ib1 = in + ((long long)b * 1020 + c) * HW;
    const __nv_bfloat16* ib2 = in + ((long long)b * 1020 + HIDDEN + c) * HW;
    float w1[9], w2[9];
#pragma unroll
    for (int i = 0; i < 9; i++) { w1[i] = w9[c * 9 + i]; w2[i] = w9[(HIDDEN + c) * 9 + i]; }
    int y = n >> 7, x = n & 127;
    float s1 = 0.f, s2 = 0.f;
#pragma unroll
    for (int ky = 0; ky < 3; ky++) {
        int iy = y + ky - 1;
        if ((unsigned)iy >= IMG_W) continue;
#pragma unroll
        for (int kx = 0; kx < 3; kx++) {
            int ix = x + kx - 1;
            if ((unsigned)ix >= IMG_W) continue;
            s1 += w1[ky * 3 + kx] * __bfloat162float(ib1[iy * IMG_W + ix]);
            s2 += w2[ky * 3 + kx] * __bfloat162float(ib2[iy * IMG_W + ix]);
        }
    }
    float g = 0.5f * s1 * (1.f + erff(s1 * 0.70710678118654752f));
    out[((long long)b * 512 + c) * HW + n] = __float2bfloat16(g * s2);
}

// =============================================================================
extern "C" void kernel_launch(void* const* d_in, const int* in_sizes, int n_in,
                              void* d_out, int out_size) {
    const float* x     = (const float*)d_in[0];
    const float* n1w   = (const float*)d_in[1];
    const float* qkvw  = (const float*)d_in[2];
    const float* qkvdw = (const float*)d_in[3];
    const float* temp  = (const float*)d_in[4];
    const float* projw = (const float*)d_in[5];
    const float* n2w   = (const float*)d_in[6];
    const float* pinw  = (const float*)d_in[7];
    const float* dww   = (const float*)d_in[8];
    const float* poutw = (const float*)d_in[9];
    float* out = (float*)d_out;

    __nv_bfloat16 *S0b, *S1b, *S2b, *Wqkv, *Wproj, *Wpin, *Wpout;
    cudaGetSymbolAddress((void**)&S0b, g_S0b);
    cudaGetSymbolAddress((void**)&S1b, g_S1b);
    cudaGetSymbolAddress((void**)&S2b, g_S2b);
    cudaGetSymbolAddress((void**)&Wqkv, g_Wqkv);
    cudaGetSymbolAddress((void**)&Wproj, g_Wproj);
    cudaGetSymbolAddress((void**)&Wpin, g_Wpin);
    cudaGetSymbolAddress((void**)&Wpout, g_Wpout);

    dim3 pxGrid(HW / 256, BATCH);

    // weight conversions (tiny)
    wconv_kernel<<<(576 * 192 + 255) / 256, 256>>>(qkvw, Wqkv, 576, 192, 576, 192);
    wconv_kernel<<<(192 * 192 + 255) / 256, 256>>>(projw, Wproj, 192, 192, 192, 192);
    wconv_kernel<<<(1024 * 192 + 255) / 256, 256>>>(pinw, Wpin, 1020, 192, 1024, 192);
    wconv_kernel<<<(192 * 512 + 255) / 256, 256>>>(poutw, Wpout, 192, 510, 192, 512);

    // ---- MDTA branch ----
    ln_apply_kernel<<<pxGrid, 256>>>(x, n1w, S2b);

    // qkv 1x1: 576x192, bf16 -> bf16
    gemm_pipe<<<dim3(HW / 256, 9, BATCH), 256>>>(
        Wqkv, S2b, S0b, nullptr, 576, 192, (long long)DIM * HW, (long long)576 * HW, 1, 0);

    dw_qkv_kernel<<<dim3(HW / 256, 576, BATCH), 256>>>(S0b, qkvdw, S1b);
    attn_part_kernel<<<dim3(16, 16), 256>>>();
    attn_finish_kernel<<<16, 256>>>(temp);
    av_kernel<<<dim3(HW / 256, 16), 256>>>();

    // proj 1x1 (192x192): bf16 -> fp32 + residual(x)
    gemm_pipe<<<dim3(HW / 256, 3, BATCH), 256>>>(
        Wproj, S2b, out, x, 192, 192, (long long)DIM * HW, (long long)DIM * HW, 0, 1);

    // ---- GDFN branch ----
    ln_apply_kernel<<<pxGrid, 256>>>(out, n2w, S2b);

    // pin 1x1 (1020x192 padded to 1024): bf16 -> bf16
    gemm_pipe<<<dim3(HW / 256, 16, BATCH), 256>>>(
        Wpin, S2b, S0b, nullptr, 1020, 192, (long long)DIM * HW, (long long)1020 * HW, 1, 0);

    dw_gate_kernel<<<dim3(HW / 256, 512, BATCH), 256>>>(S0b, dww, S1b);

    // pout 1x1 (192x512 padded K): bf16 -> fp32 + residual(d_out)
    gemm_pipe<<<dim3(HW / 256, 3, BATCH), 256>>>(
        Wpout, S1b, out, out, 192, 512, (long long)512 * HW, (long long)DIM * HW, 0, 1);
}